// round 8
// baseline (speedup 1.0000x reference)
#include <cuda_runtime.h>

#define Bx 16
#define Nx 20000
#define Kx 16
#define Lx 256
#define Hx 1024
#define NOx 60000

typedef unsigned long long ull;

// ---------------- device scratch ----------------
__device__ float d_h[Hx * Bx];        // hidden post-relu, layout [k*16 + b]
__device__ float d_recon[Bx * NOx];   // [b][j]
__device__ float d_gflat[Bx * Nx * 4];// grad wrt recon, padded [b][n*4 + c]
__device__ float d_ghid[Bx * Hx];     // [b][k]
__device__ float d_w1t[Hx * Lx];      // W1 transposed [h][l]

// ---------------- packed f32x2 helpers ----------------
static __device__ __forceinline__ ull pack2(float x, float y) {
    ull r;
    asm("mov.b64 %0,{%1,%2};" : "=l"(r) : "r"(__float_as_uint(x)), "r"(__float_as_uint(y)));
    return r;
}
static __device__ __forceinline__ void unpack2(ull v, float& x, float& y) {
    unsigned lo, hi;
    asm("mov.b64 {%0,%1},%2;" : "=r"(lo), "=r"(hi) : "l"(v));
    x = __uint_as_float(lo); y = __uint_as_float(hi);
}
static __device__ __forceinline__ ull ffma2(ull a, ull b, ull c) {
    ull d;
    asm("fma.rn.f32x2 %0,%1,%2,%3;" : "=l"(d) : "l"(a), "l"(b), "l"(c));
    return d;
}

// ---------------- prep: zero scratch, transpose W1, zero energy ----------------
__global__ void k_prep(const float* __restrict__ W1, float* __restrict__ out) {
    int i = blockIdx.x * 256 + threadIdx.x;
    if (i < Bx * Nx * 4) d_gflat[i] = 0.f;
    if (i < Bx * Hx) d_ghid[i] = 0.f;
    if (i < Lx * Hx) { int l = i >> 10, h = i & 1023; d_w1t[h * Lx + l] = W1[i]; }
    if (i < Bx) out[i] = 0.f;
}

// ---------------- h = relu(code @ W1 + b1), stored [k][b] ----------------
__global__ void __launch_bounds__(256) k_hidden(const float* __restrict__ code,
                                                const float* __restrict__ W1,
                                                const float* __restrict__ b1) {
    __shared__ float cs[Bx * Lx];
    int t = threadIdx.x;
    for (int i = t; i < Bx * Lx; i += 256) cs[i] = code[i];
    __syncthreads();
    int j = blockIdx.x * 256 + t;  // hidden index 0..1023
    float acc[Bx];
    float bj = b1[j];
#pragma unroll
    for (int b = 0; b < Bx; b++) acc[b] = bj;
    for (int l = 0; l < Lx; l++) {
        float w = W1[l * Hx + j];
#pragma unroll
        for (int b = 0; b < Bx; b++) acc[b] += cs[b * Lx + l] * w;
    }
#pragma unroll
    for (int b = 0; b < Bx; b++) d_h[j * Bx + b] = fmaxf(acc[b], 0.f);
}

// ---------------- recon = h @ W2 + b2 (streams W2 once) ----------------
__global__ void __launch_bounds__(256) k_recon(const float* __restrict__ W2,
                                               const float* __restrict__ b2) {
    __shared__ float hs[512 * Bx];  // half of h, 32 KB
    int t = threadIdx.x;
    int j0 = blockIdx.x * 512 + t;
    int j1 = j0 + 256;
    int jc0 = min(j0, NOx - 1), jc1 = min(j1, NOx - 1);
    ull a0[8], a1[8];
#pragma unroll
    for (int p = 0; p < 8; p++) { a0[p] = 0ull; a1[p] = 0ull; }
    for (int half = 0; half < 2; half++) {
        __syncthreads();
        for (int i = t; i < 512 * Bx; i += 256) hs[i] = d_h[half * 512 * Bx + i];
        __syncthreads();
        const ull* hu = (const ull*)hs;
        const float* w2r = W2 + (size_t)half * 512 * NOx;
#pragma unroll 4
        for (int k = 0; k < 512; k++) {
            float w0 = w2r[(size_t)k * NOx + jc0];
            float w1 = w2r[(size_t)k * NOx + jc1];
            ull wv0 = pack2(w0, w0), wv1 = pack2(w1, w1);
#pragma unroll
            for (int p = 0; p < 8; p++) {
                ull hv = hu[k * 8 + p];
                a0[p] = ffma2(hv, wv0, a0[p]);
                a1[p] = ffma2(hv, wv1, a1[p]);
            }
        }
    }
    float bb0 = b2[jc0], bb1 = b2[jc1];
#pragma unroll
    for (int p = 0; p < 8; p++) {
        float x, y;
        unpack2(a0[p], x, y);
        if (j0 < NOx) {
            d_recon[(size_t)(2 * p) * NOx + j0] = x + bb0;
            d_recon[(size_t)(2 * p + 1) * NOx + j0] = y + bb0;
        }
        unpack2(a1[p], x, y);
        if (j1 < NOx) {
            d_recon[(size_t)(2 * p) * NOx + j1] = x + bb1;
            d_recon[(size_t)(2 * p + 1) * NOx + j1] = y + bb1;
        }
    }
}

// ---------------- Jacobi rotation on symmetric 4x4, compile-time (P,Q) ----------------
template <int P, int Q>
static __device__ __forceinline__ void jrot(float a[4][4], float v[4][4]) {
    float apq = a[P][Q];
    if (apq != 0.f) {
        float theta = 0.5f * (a[Q][Q] - a[P][P]) / apq;
        float tt = copysignf(1.f, theta) / (fabsf(theta) + sqrtf(theta * theta + 1.f));
        float c = rsqrtf(tt * tt + 1.f);
        float s = tt * c;
        a[P][P] -= tt * apq;
        a[Q][Q] += tt * apq;
        a[P][Q] = 0.f; a[Q][P] = 0.f;
#pragma unroll
        for (int r = 0; r < 4; r++) {
            if (r == P || r == Q) continue;
            float arp = a[r][P], arq = a[r][Q];
            float nrp = c * arp - s * arq;
            float nrq = s * arp + c * arq;
            a[r][P] = nrp; a[P][r] = nrp;
            a[r][Q] = nrq; a[Q][r] = nrq;
        }
#pragma unroll
        for (int r = 0; r < 4; r++) {
            float vrp = v[r][P], vrq = v[r][Q];
            v[r][P] = c * vrp - s * vrq;
            v[r][Q] = s * vrp + c * vrq;
        }
    }
}

// ---------------- per-vertex ARAP: rotation, energy, grad wrt recon ----------------
__global__ void __launch_bounds__(128) k_arap(const float* __restrict__ xyz,
                                              const float* __restrict__ wmat,
                                              const float* __restrict__ area,
                                              const int* __restrict__ nbr,
                                              const int* __restrict__ numnb,
                                              float* __restrict__ out) {
    __shared__ float red[128];
    const float invNK = 1.f / (float)(Nx * Kx);
    int t = threadIdx.x;
    int n = blockIdx.x * 128 + t;
    int b = blockIdx.y;
    float ev = 0.f;
    if (n < Nx) {
        const float* xb = xyz + (size_t)b * Nx * 3;
        const float* rb = d_recon + (size_t)b * NOx;
        float xnx = xb[n * 3], xny = xb[n * 3 + 1], xnz = xb[n * 3 + 2];
        float rnx = rb[n * 3], rny = rb[n * 3 + 1], rnz = rb[n * 3 + 2];
        int nn = numnb[n];
        int jk[Kx]; float wk[Kx];
        const int4* nb4 = (const int4*)(nbr + n * Kx);
        const float4* wm4 = (const float4*)(wmat + n * Kx);
#pragma unroll
        for (int q = 0; q < 4; q++) {
            int4 jv = nb4[q]; float4 wv = wm4[q];
            jk[q * 4 + 0] = jv.x; jk[q * 4 + 1] = jv.y; jk[q * 4 + 2] = jv.z; jk[q * 4 + 3] = jv.w;
            wk[q * 4 + 0] = (q * 4 + 0 < nn) ? wv.x : 0.f;
            wk[q * 4 + 1] = (q * 4 + 1 < nn) ? wv.y : 0.f;
            wk[q * 4 + 2] = (q * 4 + 2 < nn) ? wv.z : 0.f;
            wk[q * 4 + 3] = (q * 4 + 3 < nn) ? wv.w : 0.f;
        }
        float S00 = 0, S01 = 0, S02 = 0, S10 = 0, S11 = 0, S12 = 0, S20 = 0, S21 = 0, S22 = 0;
#pragma unroll
        for (int k = 0; k < Kx; k++) {
            int j = jk[k]; float w = wk[k];
            float dx = xnx - xb[j * 3], dy = xny - xb[j * 3 + 1], dz = xnz - xb[j * 3 + 2];
            float qx = rnx - rb[j * 3], qy = rny - rb[j * 3 + 1], qz = rnz - rb[j * 3 + 2];
            S00 += w * dx * qx; S01 += w * dx * qy; S02 += w * dx * qz;
            S10 += w * dy * qx; S11 += w * dy * qy; S12 += w * dy * qz;
            S20 += w * dz * qx; S21 += w * dz * qy; S22 += w * dz * qz;
        }
        // Davenport/Horn 4x4 K-matrix: max eigenvector = quaternion of R (d -> dq)
        float a[4][4], v[4][4];
        a[0][0] = S00 + S11 + S22;
        a[1][1] = S00 - S11 - S22;
        a[2][2] = S11 - S00 - S22;
        a[3][3] = S22 - S00 - S11;
        a[0][1] = a[1][0] = S12 - S21;
        a[0][2] = a[2][0] = S20 - S02;
        a[0][3] = a[3][0] = S01 - S10;
        a[1][2] = a[2][1] = S01 + S10;
        a[1][3] = a[3][1] = S02 + S20;
        a[2][3] = a[3][2] = S12 + S21;
#pragma unroll
        for (int i = 0; i < 4; i++)
#pragma unroll
            for (int j2 = 0; j2 < 4; j2++) v[i][j2] = (i == j2) ? 1.f : 0.f;
#pragma unroll
        for (int sw = 0; sw < 6; sw++) {
            jrot<0, 1>(a, v); jrot<0, 2>(a, v); jrot<0, 3>(a, v);
            jrot<1, 2>(a, v); jrot<1, 3>(a, v); jrot<2, 3>(a, v);
        }
        float best = a[0][0];
        float qw = v[0][0], qx = v[1][0], qy = v[2][0], qz = v[3][0];
#pragma unroll
        for (int m = 1; m < 4; m++)
            if (a[m][m] > best) {
                best = a[m][m];
                qw = v[0][m]; qx = v[1][m]; qy = v[2][m]; qz = v[3][m];
            }
        float inv = rsqrtf(qw * qw + qx * qx + qy * qy + qz * qz);
        qw *= inv; qx *= inv; qy *= inv; qz *= inv;
        float R00 = 1.f - 2.f * (qy * qy + qz * qz);
        float R01 = 2.f * (qx * qy - qw * qz);
        float R02 = 2.f * (qx * qz + qw * qy);
        float R10 = 2.f * (qx * qy + qw * qz);
        float R11 = 1.f - 2.f * (qx * qx + qz * qz);
        float R12 = 2.f * (qy * qz - qw * qx);
        float R20 = 2.f * (qx * qz - qw * qy);
        float R21 = 2.f * (qy * qz + qw * qx);
        float R22 = 1.f - 2.f * (qx * qx + qy * qy);

        float an = area[n];
        float coef = 2.f * an * invNK;
        float gx = 0.f, gy = 0.f, gz = 0.f, es = 0.f;
        float* gb = d_gflat + (size_t)b * Nx * 4;
#pragma unroll
        for (int k = 0; k < Kx; k++) {
            int j = jk[k]; float w = wk[k];
            float dx = xnx - xb[j * 3], dy = xny - xb[j * 3 + 1], dz = xnz - xb[j * 3 + 2];
            float cx = rnx - rb[j * 3], cy = rny - rb[j * 3 + 1], cz = rnz - rb[j * 3 + 2];
            float r0 = cx - (R00 * dx + R01 * dy + R02 * dz);
            float r1 = cy - (R10 * dx + R11 * dy + R12 * dz);
            float r2 = cz - (R20 * dx + R21 * dy + R22 * dz);
            es += w * (r0 * r0 + r1 * r1 + r2 * r2);
            if (w != 0.f) {
                float g0 = coef * w * r0, g1 = coef * w * r1, g2 = coef * w * r2;
                gx += g0; gy += g1; gz += g2;
                atomicAdd((float4*)(gb + (size_t)j * 4), make_float4(-g0, -g1, -g2, 0.f));
            }
        }
        atomicAdd((float4*)(gb + (size_t)n * 4), make_float4(gx, gy, gz, 0.f));
        ev = an * es;
    }
    red[t] = ev;
    __syncthreads();
    for (int s = 64; s > 0; s >>= 1) {
        if (t < s) red[t] += red[t + s];
        __syncthreads();
    }
    if (t == 0) atomicAdd(&out[b], red[0] * invNK);
}

// ---------------- g_h = g_flat @ W2^T (streams W2 again) ----------------
__global__ void __launch_bounds__(256) k_gh(const float* __restrict__ W2) {
    __shared__ float gs[256 * 17];  // staged gflat chunk, stride-17 (conflict-free)
    int t = threadIdx.x;
    int lane = t & 31, wrp = t >> 5;
    int k0 = blockIdx.x * 32 + wrp * 4;  // this warp's 4 k-rows
    ull acc[4][8];
#pragma unroll
    for (int kk = 0; kk < 4; kk++)
#pragma unroll
        for (int p = 0; p < 8; p++) acc[kk][p] = 0ull;

    for (int c = blockIdx.y; c * 256 < NOx; c += gridDim.y) {
        int jb = c * 256;
        __syncthreads();
        for (int idx = t; idx < 256 * Bx; idx += 256) {
            int jj = idx & 255, b = idx >> 8;
            int jg = jb + jj;
            float val = 0.f;
            if (jg < NOx) {
                int nn = jg / 3, cc = jg - nn * 3;
                val = d_gflat[((size_t)b * Nx + nn) * 4 + cc];
            }
            gs[jj * 17 + b] = val;
        }
        __syncthreads();
#pragma unroll 1
        for (int it = 0; it < 8; it++) {
            int jj = it * 32 + lane;
            int jgc = min(jb + jj, NOx - 1);
            float f[Bx];
#pragma unroll
            for (int bb = 0; bb < Bx; bb++) f[bb] = gs[jj * 17 + bb];
            ull g[8];
#pragma unroll
            for (int p = 0; p < 8; p++) g[p] = pack2(f[2 * p], f[2 * p + 1]);
            const float* wp = W2 + jgc;
#pragma unroll
            for (int kk = 0; kk < 4; kk++) {
                float w = wp[(size_t)(k0 + kk) * NOx];
                ull wv = pack2(w, w);
#pragma unroll
                for (int p = 0; p < 8; p++) acc[kk][p] = ffma2(g[p], wv, acc[kk][p]);
            }
        }
    }
    // warp reduce + atomic accumulate
#pragma unroll
    for (int kk = 0; kk < 4; kk++)
#pragma unroll
        for (int p = 0; p < 8; p++) {
            float x, y;
            unpack2(acc[kk][p], x, y);
#pragma unroll
            for (int off = 16; off > 0; off >>= 1) {
                x += __shfl_xor_sync(0xFFFFFFFFu, x, off);
                y += __shfl_xor_sync(0xFFFFFFFFu, y, off);
            }
            if (lane == 0) {
                atomicAdd(&d_ghid[(2 * p) * Hx + k0 + kk], x);
                atomicAdd(&d_ghid[(2 * p + 1) * Hx + k0 + kk], y);
            }
        }
}

// ---------------- code_grad = (g_h * relu') @ W1^T ----------------
__global__ void __launch_bounds__(256) k_cgrad(float* __restrict__ out) {
    __shared__ float mg[Hx];
    int b = blockIdx.x, t = threadIdx.x;
    for (int h = t; h < Hx; h += 256)
        mg[h] = d_ghid[b * Hx + h] * (d_h[h * Bx + b] > 0.f ? 1.f : 0.f);
    __syncthreads();
    float acc = 0.f;
#pragma unroll 4
    for (int h = 0; h < Hx; h++) acc += mg[h] * d_w1t[h * Lx + t];
    out[Bx + b * Lx + t] = acc;
}

// ---------------- launch ----------------
extern "C" void kernel_launch(void* const* d_in, const int* in_sizes, int n_in,
                              void* d_out, int out_size) {
    const float* code = (const float*)d_in[0];
    const float* W1   = (const float*)d_in[1];
    const float* b1   = (const float*)d_in[2];
    const float* W2   = (const float*)d_in[3];
    const float* b2   = (const float*)d_in[4];
    const float* xyz  = (const float*)d_in[5];
    const float* wmat = (const float*)d_in[6];
    const float* area = (const float*)d_in[7];
    const int*   nbr  = (const int*)d_in[8];
    const int*   nnb  = (const int*)d_in[9];
    float* out = (float*)d_out;

    k_prep<<<(Bx * Nx * 4 + 255) / 256, 256>>>(W1, out);
    k_hidden<<<Hx / 256, 256>>>(code, W1, b1);
    k_recon<<<(NOx + 511) / 512, 256>>>(W2, b2);
    k_arap<<<dim3((Nx + 127) / 128, Bx), 128>>>(xyz, wmat, area, nbr, nnb, out);
    k_gh<<<dim3(Hx / 32, 8), 256>>>(W2);
    k_cgrad<<<Bx, 256>>>(out);
    (void)in_sizes; (void)n_in; (void)out_size;
}

// round 9
// speedup vs baseline: 1.0884x; 1.0884x over previous
#include <cuda_runtime.h>

#define Bx 16
#define Nx 20000
#define Kx 16
#define Lx 256
#define Hx 1024
#define NOx 60000

typedef unsigned long long ull;

// ---------------- device scratch ----------------
__device__ float d_h[Hx * Bx];                 // hidden post-relu, [k*16+b]
__device__ float d_rpart[4 * Bx * Nx * 4];     // recon partials [ky][b][n][4]
__device__ float d_recon4[Bx * Nx * 4];        // recon padded [b][n][4]
__device__ float d_xyz4[Bx * Nx * 4];          // xyz padded [b][n][4]
__device__ float d_quat[Bx * Nx * 4];          // quaternion per (b,n)
__device__ float d_gflat[Bx * Nx * 4];         // grad wrt recon [b][n][4]
__device__ float d_ghid[Bx * Hx];              // [b][k]
__device__ float d_w1t[Hx * Lx];               // W1^T [h][l]

// ---------------- packed f32x2 helpers ----------------
static __device__ __forceinline__ ull pack2(float x, float y) {
    ull r;
    asm("mov.b64 %0,{%1,%2};" : "=l"(r) : "r"(__float_as_uint(x)), "r"(__float_as_uint(y)));
    return r;
}
static __device__ __forceinline__ void unpack2(ull v, float& x, float& y) {
    unsigned lo, hi;
    asm("mov.b64 {%0,%1},%2;" : "=r"(lo), "=r"(hi) : "l"(v));
    x = __uint_as_float(lo); y = __uint_as_float(hi);
}
static __device__ __forceinline__ ull ffma2(ull a, ull b, ull c) {
    ull d;
    asm("fma.rn.f32x2 %0,%1,%2,%3;" : "=l"(d) : "l"(a), "l"(b), "l"(c));
    return d;
}

// ---------------- prep: zero scratch, transpose W1, pad xyz, zero out ----------------
__global__ void k_prep(const float* __restrict__ W1, const float* __restrict__ xyz,
                       float* __restrict__ out) {
    int i = blockIdx.x * 256 + threadIdx.x;
    if (i < Bx * Nx * 4) d_gflat[i] = 0.f;
    if (i < Bx * Nx) {
        d_xyz4[i * 4 + 0] = xyz[i * 3 + 0];
        d_xyz4[i * 4 + 1] = xyz[i * 3 + 1];
        d_xyz4[i * 4 + 2] = xyz[i * 3 + 2];
        d_xyz4[i * 4 + 3] = 0.f;
    }
    if (i < Lx * Hx) { int l = i >> 10, h = i & 1023; d_w1t[h * Lx + l] = W1[i]; }
    if (i < Bx * Hx) d_ghid[i] = 0.f;
    if (i < Bx + Bx * Lx) out[i] = 0.f;
}

// ---------------- h = relu(code @ W1 + b1), stored [k][b] ----------------
__global__ void __launch_bounds__(256) k_hidden(const float* __restrict__ code,
                                                const float* __restrict__ W1,
                                                const float* __restrict__ b1) {
    __shared__ float cs[Bx * Lx];
    int t = threadIdx.x;
    for (int i = t; i < Bx * Lx; i += 256) cs[i] = code[i];
    __syncthreads();
    int j = blockIdx.x * 256 + t;
    float acc[Bx];
    float bj = b1[j];
#pragma unroll
    for (int b = 0; b < Bx; b++) acc[b] = bj;
#pragma unroll 8
    for (int l = 0; l < Lx; l++) {
        float w = W1[l * Hx + j];
#pragma unroll
        for (int b = 0; b < Bx; b++) acc[b] += cs[b * Lx + l] * w;
    }
#pragma unroll
    for (int b = 0; b < Bx; b++) d_h[j * Bx + b] = fmaxf(acc[b], 0.f);
}

// ---------------- recon partials: each (bx,ky) block does 768 j x 256 k ----------------
__global__ void __launch_bounds__(256) k_recon(const float* __restrict__ W2) {
    __shared__ __align__(16) float hs[256 * 16];  // 16 KB h chunk [k][b]
    int t = threadIdx.x;
    int ky = blockIdx.y;
    for (int i = t; i < 256 * 16; i += 256) hs[i] = d_h[ky * 256 * 16 + i];
    __syncthreads();
    int jb = blockIdx.x * 768 + t;
    int jc0 = min(jb, NOx - 1), jc1 = min(jb + 256, NOx - 1), jc2 = min(jb + 512, NOx - 1);
    const float* wp = W2 + (size_t)ky * 256 * NOx;
    ull acc[3][8];
#pragma unroll
    for (int jj = 0; jj < 3; jj++)
#pragma unroll
        for (int p = 0; p < 8; p++) acc[jj][p] = 0ull;
    const ulonglong2* hu = (const ulonglong2*)hs;
#pragma unroll 4
    for (int k = 0; k < 256; k++) {
        float w0 = wp[(size_t)k * NOx + jc0];
        float w1 = wp[(size_t)k * NOx + jc1];
        float w2 = wp[(size_t)k * NOx + jc2];
        ulonglong2 ha = hu[k * 4 + 0], hb = hu[k * 4 + 1];
        ulonglong2 hc = hu[k * 4 + 2], hd = hu[k * 4 + 3];
        ull hv[8] = {ha.x, ha.y, hb.x, hb.y, hc.x, hc.y, hd.x, hd.y};
        ull wv0 = pack2(w0, w0), wv1 = pack2(w1, w1), wv2 = pack2(w2, w2);
#pragma unroll
        for (int p = 0; p < 8; p++) {
            acc[0][p] = ffma2(hv[p], wv0, acc[0][p]);
            acc[1][p] = ffma2(hv[p], wv1, acc[1][p]);
            acc[2][p] = ffma2(hv[p], wv2, acc[2][p]);
        }
    }
#pragma unroll
    for (int jj = 0; jj < 3; jj++) {
        int j = jb + jj * 256;
        if (j < NOx) {
            int n = j / 3, c = j - 3 * n;
            size_t base = ((size_t)ky * Bx * Nx + n) * 4 + c;
#pragma unroll
            for (int p = 0; p < 8; p++) {
                float x, y;
                unpack2(acc[jj][p], x, y);
                d_rpart[base + (size_t)(2 * p) * Nx * 4] = x;
                d_rpart[base + (size_t)(2 * p + 1) * Nx * 4] = y;
            }
        }
    }
}

// ---------------- combine partials + bias -> padded recon ----------------
__global__ void k_comb(const float* __restrict__ b2) {
    int i = blockIdx.x * 256 + threadIdx.x;  // b*Nx + n
    if (i >= Bx * Nx) return;
    int n = i % Nx;
    float x = 0.f, y = 0.f, z = 0.f;
#pragma unroll
    for (int ky = 0; ky < 4; ky++) {
        const float* p = d_rpart + ((size_t)ky * Bx * Nx + i) * 4;
        x += p[0]; y += p[1]; z += p[2];
    }
    float4 r;
    r.x = x + b2[n * 3 + 0];
    r.y = y + b2[n * 3 + 1];
    r.z = z + b2[n * 3 + 2];
    r.w = 0.f;
    ((float4*)d_recon4)[i] = r;
}

// ---------------- Jacobi rotation on symmetric 4x4, compile-time (P,Q) ----------------
template <int P, int Q>
static __device__ __forceinline__ void jrot(float a[4][4], float v[4][4]) {
    float apq = a[P][Q];
    if (apq != 0.f) {
        float theta = 0.5f * (a[Q][Q] - a[P][P]) / apq;
        float tt = copysignf(1.f, theta) / (fabsf(theta) + sqrtf(theta * theta + 1.f));
        float c = rsqrtf(tt * tt + 1.f);
        float s = tt * c;
        a[P][P] -= tt * apq;
        a[Q][Q] += tt * apq;
        a[P][Q] = 0.f; a[Q][P] = 0.f;
#pragma unroll
        for (int r = 0; r < 4; r++) {
            if (r == P || r == Q) continue;
            float arp = a[r][P], arq = a[r][Q];
            float nrp = c * arp - s * arq;
            float nrq = s * arp + c * arq;
            a[r][P] = nrp; a[P][r] = nrp;
            a[r][Q] = nrq; a[Q][r] = nrq;
        }
#pragma unroll
        for (int r = 0; r < 4; r++) {
            float vrp = v[r][P], vrq = v[r][Q];
            v[r][P] = c * vrp - s * vrq;
            v[r][Q] = s * vrp + c * vrq;
        }
    }
}

// ---------------- per-vertex best-fit rotation -> quaternion ----------------
__global__ void __launch_bounds__(256) k_rot(const float* __restrict__ wmat,
                                             const int* __restrict__ nbr,
                                             const int* __restrict__ numnb) {
    int t = threadIdx.x;
    int n = blockIdx.x * 256 + t;
    int b = blockIdx.y;
    if (n >= Nx) return;
    const float4* xb = ((const float4*)d_xyz4) + (size_t)b * Nx;
    const float4* rb = ((const float4*)d_recon4) + (size_t)b * Nx;
    float4 xn = xb[n], rn = rb[n];
    int nn = numnb[n];
    const int4* nb4 = (const int4*)(nbr + n * Kx);
    const float4* wm4 = (const float4*)(wmat + n * Kx);
    float S00 = 0, S01 = 0, S02 = 0, S10 = 0, S11 = 0, S12 = 0, S20 = 0, S21 = 0, S22 = 0;
#pragma unroll
    for (int q = 0; q < 4; q++) {
        int4 jv = nb4[q]; float4 wv = wm4[q];
        int js[4] = {jv.x, jv.y, jv.z, jv.w};
        float ws[4];
        ws[0] = (q * 4 + 0 < nn) ? wv.x : 0.f;
        ws[1] = (q * 4 + 1 < nn) ? wv.y : 0.f;
        ws[2] = (q * 4 + 2 < nn) ? wv.z : 0.f;
        ws[3] = (q * 4 + 3 < nn) ? wv.w : 0.f;
#pragma unroll
        for (int u = 0; u < 4; u++) {
            float4 xj = xb[js[u]], rj = rb[js[u]];
            float w = ws[u];
            float dx = xn.x - xj.x, dy = xn.y - xj.y, dz = xn.z - xj.z;
            float qx = rn.x - rj.x, qy = rn.y - rj.y, qz = rn.z - rj.z;
            S00 += w * dx * qx; S01 += w * dx * qy; S02 += w * dx * qz;
            S10 += w * dy * qx; S11 += w * dy * qy; S12 += w * dy * qz;
            S20 += w * dz * qx; S21 += w * dz * qy; S22 += w * dz * qz;
        }
    }
    float a[4][4], v[4][4];
    a[0][0] = S00 + S11 + S22;
    a[1][1] = S00 - S11 - S22;
    a[2][2] = S11 - S00 - S22;
    a[3][3] = S22 - S00 - S11;
    a[0][1] = a[1][0] = S12 - S21;
    a[0][2] = a[2][0] = S20 - S02;
    a[0][3] = a[3][0] = S01 - S10;
    a[1][2] = a[2][1] = S01 + S10;
    a[1][3] = a[3][1] = S02 + S20;
    a[2][3] = a[3][2] = S12 + S21;
#pragma unroll
    for (int i = 0; i < 4; i++)
#pragma unroll
        for (int j2 = 0; j2 < 4; j2++) v[i][j2] = (i == j2) ? 1.f : 0.f;
#pragma unroll
    for (int sw = 0; sw < 6; sw++) {
        jrot<0, 1>(a, v); jrot<0, 2>(a, v); jrot<0, 3>(a, v);
        jrot<1, 2>(a, v); jrot<1, 3>(a, v); jrot<2, 3>(a, v);
    }
    float best = a[0][0];
    float qw = v[0][0], qx = v[1][0], qy = v[2][0], qz = v[3][0];
#pragma unroll
    for (int m = 1; m < 4; m++)
        if (a[m][m] > best) {
            best = a[m][m];
            qw = v[0][m]; qx = v[1][m]; qy = v[2][m]; qz = v[3][m];
        }
    float inv = rsqrtf(qw * qw + qx * qx + qy * qy + qz * qz);
    ((float4*)d_quat)[(size_t)b * Nx + n] = make_float4(qw * inv, qx * inv, qy * inv, qz * inv);
}

// ---------------- energy + grad wrt recon ----------------
__global__ void __launch_bounds__(256) k_grad(const float* __restrict__ wmat,
                                              const float* __restrict__ area,
                                              const int* __restrict__ nbr,
                                              const int* __restrict__ numnb,
                                              float* __restrict__ out) {
    __shared__ float red[256];
    const float invNK = 1.f / (float)(Nx * Kx);
    int t = threadIdx.x;
    int n = blockIdx.x * 256 + t;
    int b = blockIdx.y;
    float ev = 0.f;
    if (n < Nx) {
        const float4* xb = ((const float4*)d_xyz4) + (size_t)b * Nx;
        const float4* rb = ((const float4*)d_recon4) + (size_t)b * Nx;
        float4 xn = xb[n], rn = rb[n];
        int nn = numnb[n];
        const int4* nb4 = (const int4*)(nbr + n * Kx);
        const float4* wm4 = (const float4*)(wmat + n * Kx);
        float4 qv = ((const float4*)d_quat)[(size_t)b * Nx + n];
        float qw = qv.x, qx = qv.y, qy = qv.z, qz = qv.w;
        float R00 = 1.f - 2.f * (qy * qy + qz * qz);
        float R01 = 2.f * (qx * qy - qw * qz);
        float R02 = 2.f * (qx * qz + qw * qy);
        float R10 = 2.f * (qx * qy + qw * qz);
        float R11 = 1.f - 2.f * (qx * qx + qz * qz);
        float R12 = 2.f * (qy * qz - qw * qx);
        float R20 = 2.f * (qx * qz - qw * qy);
        float R21 = 2.f * (qy * qz + qw * qx);
        float R22 = 1.f - 2.f * (qx * qx + qy * qy);
        float an = area[n];
        float coef = 2.f * an * invNK;
        float gx = 0.f, gy = 0.f, gz = 0.f, es = 0.f;
        float4* gb4 = ((float4*)d_gflat) + (size_t)b * Nx;
#pragma unroll
        for (int q = 0; q < 4; q++) {
            int4 jv = nb4[q]; float4 wv = wm4[q];
            int js[4] = {jv.x, jv.y, jv.z, jv.w};
            float ws[4];
            ws[0] = (q * 4 + 0 < nn) ? wv.x : 0.f;
            ws[1] = (q * 4 + 1 < nn) ? wv.y : 0.f;
            ws[2] = (q * 4 + 2 < nn) ? wv.z : 0.f;
            ws[3] = (q * 4 + 3 < nn) ? wv.w : 0.f;
#pragma unroll
            for (int u = 0; u < 4; u++) {
                int j = js[u]; float w = ws[u];
                float4 xj = xb[j], rj = rb[j];
                float dx = xn.x - xj.x, dy = xn.y - xj.y, dz = xn.z - xj.z;
                float cx = rn.x - rj.x, cy = rn.y - rj.y, cz = rn.z - rj.z;
                float r0 = cx - (R00 * dx + R01 * dy + R02 * dz);
                float r1 = cy - (R10 * dx + R11 * dy + R12 * dz);
                float r2 = cz - (R20 * dx + R21 * dy + R22 * dz);
                es += w * (r0 * r0 + r1 * r1 + r2 * r2);
                if (w != 0.f) {
                    float g0 = coef * w * r0, g1 = coef * w * r1, g2 = coef * w * r2;
                    gx += g0; gy += g1; gz += g2;
                    atomicAdd(&gb4[j], make_float4(-g0, -g1, -g2, 0.f));
                }
            }
        }
        atomicAdd(&gb4[n], make_float4(gx, gy, gz, 0.f));
        ev = an * es;
    }
    red[t] = ev;
    __syncthreads();
    for (int s = 128; s > 0; s >>= 1) {
        if (t < s) red[t] += red[t + s];
        __syncthreads();
    }
    if (t == 0) atomicAdd(&out[b], red[0] * (1.f / (float)(Nx * Kx)));
}

// ---------------- g_h = g_flat @ W2^T (streams W2 again) ----------------
__global__ void __launch_bounds__(256) k_gh(const float* __restrict__ W2) {
    __shared__ ull gs[256 * 9];  // staged g packed as ull, 18 KB
    int t = threadIdx.x;
    int lane = t & 31, wrp = t >> 5;
    int k0 = blockIdx.x * 32 + wrp * 4;
    ull acc[4][8];
#pragma unroll
    for (int kk = 0; kk < 4; kk++)
#pragma unroll
        for (int p = 0; p < 8; p++) acc[kk][p] = 0ull;

    for (int jb = blockIdx.y * 256; jb < NOx; jb += gridDim.y * 256) {
        __syncthreads();
        int jg = jb + t;
        int nv = 0, cv = 0;
        bool valid = jg < NOx;
        if (valid) { nv = jg / 3; cv = jg - 3 * nv; }
#pragma unroll
        for (int p = 0; p < 8; p++) {
            float v0 = 0.f, v1 = 0.f;
            if (valid) {
                v0 = d_gflat[((size_t)(2 * p) * Nx + nv) * 4 + cv];
                v1 = d_gflat[((size_t)(2 * p + 1) * Nx + nv) * 4 + cv];
            }
            gs[t * 9 + p] = pack2(v0, v1);
        }
        __syncthreads();
#pragma unroll 1
        for (int it = 0; it < 8; it++) {
            int jj = it * 32 + lane;
            int jgc = min(jb + jj, NOx - 1);
            ull g[8];
#pragma unroll
            for (int p = 0; p < 8; p++) g[p] = gs[jj * 9 + p];
            const float* wp = W2 + jgc;
            float w[4];
#pragma unroll
            for (int kk = 0; kk < 4; kk++) w[kk] = wp[(size_t)(k0 + kk) * NOx];
#pragma unroll
            for (int kk = 0; kk < 4; kk++) {
                ull wv = pack2(w[kk], w[kk]);
#pragma unroll
                for (int p = 0; p < 8; p++) acc[kk][p] = ffma2(g[p], wv, acc[kk][p]);
            }
        }
    }
#pragma unroll
    for (int kk = 0; kk < 4; kk++)
#pragma unroll
        for (int p = 0; p < 8; p++) {
            float x, y;
            unpack2(acc[kk][p], x, y);
#pragma unroll
            for (int off = 16; off > 0; off >>= 1) {
                x += __shfl_xor_sync(0xFFFFFFFFu, x, off);
                y += __shfl_xor_sync(0xFFFFFFFFu, y, off);
            }
            if (lane == 0) {
                atomicAdd(&d_ghid[(2 * p) * Hx + k0 + kk], x);
                atomicAdd(&d_ghid[(2 * p + 1) * Hx + k0 + kk], y);
            }
        }
}

// ---------------- code_grad = (g_h * relu') @ W1^T ----------------
__global__ void __launch_bounds__(256) k_cgrad(float* __restrict__ out) {
    __shared__ float mg[128];
    int b = blockIdx.x, hg = blockIdx.y, t = threadIdx.x;
    if (t < 128) {
        int h = hg * 128 + t;
        mg[t] = d_ghid[b * Hx + h] * (d_h[h * Bx + b] > 0.f ? 1.f : 0.f);
    }
    __syncthreads();
    float acc = 0.f;
#pragma unroll 8
    for (int hh = 0; hh < 128; hh++) acc += mg[hh] * d_w1t[(hg * 128 + hh) * Lx + t];
    atomicAdd(&out[Bx + b * Lx + t], acc);
}

// ---------------- launch ----------------
extern "C" void kernel_launch(void* const* d_in, const int* in_sizes, int n_in,
                              void* d_out, int out_size) {
    const float* code = (const float*)d_in[0];
    const float* W1   = (const float*)d_in[1];
    const float* b1   = (const float*)d_in[2];
    const float* W2   = (const float*)d_in[3];
    const float* b2   = (const float*)d_in[4];
    const float* xyz  = (const float*)d_in[5];
    const float* wmat = (const float*)d_in[6];
    const float* area = (const float*)d_in[7];
    const int*   nbr  = (const int*)d_in[8];
    const int*   nnb  = (const int*)d_in[9];
    float* out = (float*)d_out;

    k_prep<<<(Bx * Nx * 4 + 255) / 256, 256>>>(W1, xyz, out);
    k_hidden<<<Hx / 256, 256>>>(code, W1, b1);
    k_recon<<<dim3(79, 4), 256>>>(W2);
    k_comb<<<(Bx * Nx + 255) / 256, 256>>>(b2);
    k_rot<<<dim3(79, Bx), 256>>>(wmat, nbr, nnb);
    k_grad<<<dim3(79, Bx), 256>>>(wmat, area, nbr, nnb, out);
    k_gh<<<dim3(32, 8), 256>>>(W2);
    k_cgrad<<<dim3(Bx, 8), 256>>>(out);
    (void)in_sizes; (void)n_in; (void)out_size;
}

// round 10
// speedup vs baseline: 1.4972x; 1.3757x over previous
#include <cuda_runtime.h>

#define Bx 16
#define Nx 20000
#define Kx 16
#define Lx 256
#define Hx 1024
#define NOx 60000
#define NQ (NOx / 4)   // 15000 float4 per W2 row

typedef unsigned long long ull;

// ---------------- device scratch ----------------
__device__ float d_h[Hx * Bx];                 // hidden post-relu, [k*16+b]
__device__ float d_rpart[4 * Bx * Nx * 4];     // recon partials [ky][b][n][4]
__device__ float d_recon4[Bx * Nx * 4];        // recon padded [b][n][4]
__device__ float d_xyz4[Bx * Nx * 4];          // xyz padded [b][n][4]
__device__ float d_quat[Bx * Nx * 4];          // quaternion per (b,n)
__device__ float d_gflat[Bx * Nx * 4];         // grad wrt recon [b][n][4]
__device__ float d_ghid[Bx * Hx];              // [b][k]
__device__ float d_w1t[Hx * Lx];               // W1^T [h][l]

// ---------------- packed f32x2 helpers ----------------
static __device__ __forceinline__ ull pack2(float x, float y) {
    ull r;
    asm("mov.b64 %0,{%1,%2};" : "=l"(r) : "r"(__float_as_uint(x)), "r"(__float_as_uint(y)));
    return r;
}
static __device__ __forceinline__ void unpack2(ull v, float& x, float& y) {
    unsigned lo, hi;
    asm("mov.b64 {%0,%1},%2;" : "=r"(lo), "=r"(hi) : "l"(v));
    x = __uint_as_float(lo); y = __uint_as_float(hi);
}
static __device__ __forceinline__ ull ffma2(ull a, ull b, ull c) {
    ull d;
    asm("fma.rn.f32x2 %0,%1,%2,%3;" : "=l"(d) : "l"(a), "l"(b), "l"(c));
    return d;
}

// ---------------- prep: zero scratch, transpose W1, pad xyz, zero out ----------------
__global__ void k_prep(const float* __restrict__ W1, const float* __restrict__ xyz,
                       float* __restrict__ out) {
    int i = blockIdx.x * 256 + threadIdx.x;
    if (i < Bx * Nx * 4) d_gflat[i] = 0.f;
    if (i < Bx * Nx) {
        d_xyz4[i * 4 + 0] = xyz[i * 3 + 0];
        d_xyz4[i * 4 + 1] = xyz[i * 3 + 1];
        d_xyz4[i * 4 + 2] = xyz[i * 3 + 2];
        d_xyz4[i * 4 + 3] = 0.f;
    }
    if (i < Lx * Hx) { int l = i >> 10, h = i & 1023; d_w1t[h * Lx + l] = W1[i]; }
    if (i < Bx * Hx) d_ghid[i] = 0.f;
    if (i < Bx + Bx * Lx) out[i] = 0.f;
}

// ---------------- h = relu(code @ W1 + b1), stored [k][b] ----------------
__global__ void __launch_bounds__(256) k_hidden(const float* __restrict__ code,
                                                const float* __restrict__ W1,
                                                const float* __restrict__ b1) {
    __shared__ float cs[Bx * Lx];
    int t = threadIdx.x;
    for (int i = t; i < Bx * Lx; i += 256) cs[i] = code[i];
    __syncthreads();
    int j = blockIdx.x * 256 + t;
    float acc[Bx];
    float bj = b1[j];
#pragma unroll
    for (int b = 0; b < Bx; b++) acc[b] = bj;
#pragma unroll 8
    for (int l = 0; l < Lx; l++) {
        float w = W1[l * Hx + j];
#pragma unroll
        for (int b = 0; b < Bx; b++) acc[b] += cs[b * Lx + l] * w;
    }
#pragma unroll
    for (int b = 0; b < Bx; b++) d_h[j * Bx + b] = fmaxf(acc[b], 0.f);
}

// ---------------- recon partials: thread owns 4 consecutive j (LDG.128 of W2) ----------------
__global__ void __launch_bounds__(256, 2) k_recon(const float* __restrict__ W2) {
    __shared__ __align__(16) float hs[256 * 16];  // 16 KB h chunk [k][b]
    int t = threadIdx.x;
    int ky = blockIdx.y;
    for (int i = t; i < 256 * 16; i += 256) hs[i] = d_h[ky * 256 * 16 + i];
    __syncthreads();
    int q = blockIdx.x * 256 + t;           // float4 column index
    int qc = min(q, NQ - 1);
    const float4* wq = (const float4*)(W2 + (size_t)ky * 256 * NOx);
    const ulonglong2* hu = (const ulonglong2*)hs;
    ull acc[4][8];
#pragma unroll
    for (int jj = 0; jj < 4; jj++)
#pragma unroll
        for (int p = 0; p < 8; p++) acc[jj][p] = 0ull;

    for (int k4 = 0; k4 < 256; k4 += 4) {
        float4 w[4];
#pragma unroll
        for (int u = 0; u < 4; u++) w[u] = wq[(size_t)(k4 + u) * NQ + qc];
#pragma unroll
        for (int u = 0; u < 4; u++) {
            int k = k4 + u;
            ulonglong2 ha = hu[k * 4 + 0], hb = hu[k * 4 + 1];
            ulonglong2 hc = hu[k * 4 + 2], hd = hu[k * 4 + 3];
            ull hv[8] = {ha.x, ha.y, hb.x, hb.y, hc.x, hc.y, hd.x, hd.y};
            ull w0 = pack2(w[u].x, w[u].x), w1 = pack2(w[u].y, w[u].y);
            ull w2v = pack2(w[u].z, w[u].z), w3 = pack2(w[u].w, w[u].w);
#pragma unroll
            for (int p = 0; p < 8; p++) {
                acc[0][p] = ffma2(hv[p], w0, acc[0][p]);
                acc[1][p] = ffma2(hv[p], w1, acc[1][p]);
                acc[2][p] = ffma2(hv[p], w2v, acc[2][p]);
                acc[3][p] = ffma2(hv[p], w3, acc[3][p]);
            }
        }
    }
    if (q < NQ) {
#pragma unroll
        for (int jj = 0; jj < 4; jj++) {
            int j = 4 * q + jj;
            int n = j / 3, c = j - 3 * n;
            float* dst = d_rpart + ((size_t)ky * Bx * Nx + n) * 4 + c;
#pragma unroll
            for (int p = 0; p < 8; p++) {
                float x, y;
                unpack2(acc[jj][p], x, y);
                dst[(size_t)(2 * p) * Nx * 4] = x;
                dst[(size_t)(2 * p + 1) * Nx * 4] = y;
            }
        }
    }
}

// ---------------- combine partials + bias -> padded recon ----------------
__global__ void k_comb(const float* __restrict__ b2) {
    int i = blockIdx.x * 256 + threadIdx.x;  // b*Nx + n
    if (i >= Bx * Nx) return;
    int n = i % Nx;
    float x = 0.f, y = 0.f, z = 0.f;
#pragma unroll
    for (int ky = 0; ky < 4; ky++) {
        const float* p = d_rpart + ((size_t)ky * Bx * Nx + i) * 4;
        x += p[0]; y += p[1]; z += p[2];
    }
    float4 r;
    r.x = x + b2[n * 3 + 0];
    r.y = y + b2[n * 3 + 1];
    r.z = z + b2[n * 3 + 2];
    r.w = 0.f;
    ((float4*)d_recon4)[i] = r;
}

// ---------------- Jacobi rotation on symmetric 4x4, compile-time (P,Q) ----------------
template <int P, int Q>
static __device__ __forceinline__ void jrot(float a[4][4], float v[4][4]) {
    float apq = a[P][Q];
    if (apq != 0.f) {
        float theta = 0.5f * (a[Q][Q] - a[P][P]) / apq;
        float tt = copysignf(1.f, theta) / (fabsf(theta) + sqrtf(theta * theta + 1.f));
        float c = rsqrtf(tt * tt + 1.f);
        float s = tt * c;
        a[P][P] -= tt * apq;
        a[Q][Q] += tt * apq;
        a[P][Q] = 0.f; a[Q][P] = 0.f;
#pragma unroll
        for (int r = 0; r < 4; r++) {
            if (r == P || r == Q) continue;
            float arp = a[r][P], arq = a[r][Q];
            float nrp = c * arp - s * arq;
            float nrq = s * arp + c * arq;
            a[r][P] = nrp; a[P][r] = nrp;
            a[r][Q] = nrq; a[Q][r] = nrq;
        }
#pragma unroll
        for (int r = 0; r < 4; r++) {
            float vrp = v[r][P], vrq = v[r][Q];
            v[r][P] = c * vrp - s * vrq;
            v[r][Q] = s * vrp + c * vrq;
        }
    }
}

// ---------------- per-vertex best-fit rotation -> quaternion ----------------
__global__ void __launch_bounds__(256) k_rot(const float* __restrict__ wmat,
                                             const int* __restrict__ nbr,
                                             const int* __restrict__ numnb) {
    int t = threadIdx.x;
    int n = blockIdx.x * 256 + t;
    int b = blockIdx.y;
    if (n >= Nx) return;
    const float4* xb = ((const float4*)d_xyz4) + (size_t)b * Nx;
    const float4* rb = ((const float4*)d_recon4) + (size_t)b * Nx;
    float4 xn = xb[n], rn = rb[n];
    int nn = numnb[n];
    const int4* nb4 = (const int4*)(nbr + n * Kx);
    const float4* wm4 = (const float4*)(wmat + n * Kx);
    float S00 = 0, S01 = 0, S02 = 0, S10 = 0, S11 = 0, S12 = 0, S20 = 0, S21 = 0, S22 = 0;
#pragma unroll
    for (int q = 0; q < 4; q++) {
        int4 jv = nb4[q]; float4 wv = wm4[q];
        int js[4] = {jv.x, jv.y, jv.z, jv.w};
        float ws[4];
        ws[0] = (q * 4 + 0 < nn) ? wv.x : 0.f;
        ws[1] = (q * 4 + 1 < nn) ? wv.y : 0.f;
        ws[2] = (q * 4 + 2 < nn) ? wv.z : 0.f;
        ws[3] = (q * 4 + 3 < nn) ? wv.w : 0.f;
#pragma unroll
        for (int u = 0; u < 4; u++) {
            float4 xj = xb[js[u]], rj = rb[js[u]];
            float w = ws[u];
            float dx = xn.x - xj.x, dy = xn.y - xj.y, dz = xn.z - xj.z;
            float qx = rn.x - rj.x, qy = rn.y - rj.y, qz = rn.z - rj.z;
            S00 += w * dx * qx; S01 += w * dx * qy; S02 += w * dx * qz;
            S10 += w * dy * qx; S11 += w * dy * qy; S12 += w * dy * qz;
            S20 += w * dz * qx; S21 += w * dz * qy; S22 += w * dz * qz;
        }
    }
    float a[4][4], v[4][4];
    a[0][0] = S00 + S11 + S22;
    a[1][1] = S00 - S11 - S22;
    a[2][2] = S11 - S00 - S22;
    a[3][3] = S22 - S00 - S11;
    a[0][1] = a[1][0] = S12 - S21;
    a[0][2] = a[2][0] = S20 - S02;
    a[0][3] = a[3][0] = S01 - S10;
    a[1][2] = a[2][1] = S01 + S10;
    a[1][3] = a[3][1] = S02 + S20;
    a[2][3] = a[3][2] = S12 + S21;
#pragma unroll
    for (int i = 0; i < 4; i++)
#pragma unroll
        for (int j2 = 0; j2 < 4; j2++) v[i][j2] = (i == j2) ? 1.f : 0.f;
#pragma unroll
    for (int sw = 0; sw < 6; sw++) {
        jrot<0, 1>(a, v); jrot<0, 2>(a, v); jrot<0, 3>(a, v);
        jrot<1, 2>(a, v); jrot<1, 3>(a, v); jrot<2, 3>(a, v);
    }
    float best = a[0][0];
    float qw = v[0][0], qx = v[1][0], qy = v[2][0], qz = v[3][0];
#pragma unroll
    for (int m = 1; m < 4; m++)
        if (a[m][m] > best) {
            best = a[m][m];
            qw = v[0][m]; qx = v[1][m]; qy = v[2][m]; qz = v[3][m];
        }
    float inv = rsqrtf(qw * qw + qx * qx + qy * qy + qz * qz);
    ((float4*)d_quat)[(size_t)b * Nx + n] = make_float4(qw * inv, qx * inv, qy * inv, qz * inv);
}

// ---------------- energy + grad wrt recon ----------------
__global__ void __launch_bounds__(256) k_grad(const float* __restrict__ wmat,
                                              const float* __restrict__ area,
                                              const int* __restrict__ nbr,
                                              const int* __restrict__ numnb,
                                              float* __restrict__ out) {
    __shared__ float red[256];
    const float invNK = 1.f / (float)(Nx * Kx);
    int t = threadIdx.x;
    int n = blockIdx.x * 256 + t;
    int b = blockIdx.y;
    float ev = 0.f;
    if (n < Nx) {
        const float4* xb = ((const float4*)d_xyz4) + (size_t)b * Nx;
        const float4* rb = ((const float4*)d_recon4) + (size_t)b * Nx;
        float4 xn = xb[n], rn = rb[n];
        int nn = numnb[n];
        const int4* nb4 = (const int4*)(nbr + n * Kx);
        const float4* wm4 = (const float4*)(wmat + n * Kx);
        float4 qv = ((const float4*)d_quat)[(size_t)b * Nx + n];
        float qw = qv.x, qx = qv.y, qy = qv.z, qz = qv.w;
        float R00 = 1.f - 2.f * (qy * qy + qz * qz);
        float R01 = 2.f * (qx * qy - qw * qz);
        float R02 = 2.f * (qx * qz + qw * qy);
        float R10 = 2.f * (qx * qy + qw * qz);
        float R11 = 1.f - 2.f * (qx * qx + qz * qz);
        float R12 = 2.f * (qy * qz - qw * qx);
        float R20 = 2.f * (qx * qz - qw * qy);
        float R21 = 2.f * (qy * qz + qw * qx);
        float R22 = 1.f - 2.f * (qx * qx + qy * qy);
        float an = area[n];
        float coef = 2.f * an * invNK;
        float gx = 0.f, gy = 0.f, gz = 0.f, es = 0.f;
        float4* gb4 = ((float4*)d_gflat) + (size_t)b * Nx;
#pragma unroll
        for (int q = 0; q < 4; q++) {
            int4 jv = nb4[q]; float4 wv = wm4[q];
            int js[4] = {jv.x, jv.y, jv.z, jv.w};
            float ws[4];
            ws[0] = (q * 4 + 0 < nn) ? wv.x : 0.f;
            ws[1] = (q * 4 + 1 < nn) ? wv.y : 0.f;
            ws[2] = (q * 4 + 2 < nn) ? wv.z : 0.f;
            ws[3] = (q * 4 + 3 < nn) ? wv.w : 0.f;
#pragma unroll
            for (int u = 0; u < 4; u++) {
                int j = js[u]; float w = ws[u];
                float4 xj = xb[j], rj = rb[j];
                float dx = xn.x - xj.x, dy = xn.y - xj.y, dz = xn.z - xj.z;
                float cx = rn.x - rj.x, cy = rn.y - rj.y, cz = rn.z - rj.z;
                float r0 = cx - (R00 * dx + R01 * dy + R02 * dz);
                float r1 = cy - (R10 * dx + R11 * dy + R12 * dz);
                float r2 = cz - (R20 * dx + R21 * dy + R22 * dz);
                es += w * (r0 * r0 + r1 * r1 + r2 * r2);
                if (w != 0.f) {
                    float g0 = coef * w * r0, g1 = coef * w * r1, g2 = coef * w * r2;
                    gx += g0; gy += g1; gz += g2;
                    atomicAdd(&gb4[j], make_float4(-g0, -g1, -g2, 0.f));
                }
            }
        }
        atomicAdd(&gb4[n], make_float4(gx, gy, gz, 0.f));
        ev = an * es;
    }
    red[t] = ev;
    __syncthreads();
    for (int s = 128; s > 0; s >>= 1) {
        if (t < s) red[t] += red[t + s];
        __syncthreads();
    }
    if (t == 0) atomicAdd(&out[b], red[0] * (1.f / (float)(Nx * Kx)));
}

// ---------------- g_h = g_flat @ W2^T (streams W2 again) ----------------
#define GHW 128
__global__ void __launch_bounds__(256, 2) k_gh(const float* __restrict__ W2) {
    __shared__ ull gs[8 * GHW];  // [p][jwin], 8 KB, conflict-free
    int t = threadIdx.x;
    int lane = t & 31, wrp = t >> 5;
    int k0 = blockIdx.x * 32 + wrp * 4;
    ull acc[4][8];
#pragma unroll
    for (int u = 0; u < 4; u++)
#pragma unroll
        for (int p = 0; p < 8; p++) acc[u][p] = 0ull;

    for (int jb = blockIdx.y * GHW; jb < NOx; jb += gridDim.y * GHW) {
        __syncthreads();
        for (int idx = t; idx < 8 * GHW; idx += 256) {
            int p = idx >> 7, jj = idx & (GHW - 1);
            int j = jb + jj;
            float v0 = 0.f, v1 = 0.f;
            if (j < NOx) {
                int n = j / 3, c = j - 3 * n;
                v0 = d_gflat[((size_t)(2 * p) * Nx + n) * 4 + c];
                v1 = d_gflat[((size_t)(2 * p + 1) * Nx + n) * 4 + c];
            }
            gs[idx] = pack2(v0, v1);
        }
        __syncthreads();
        float wv[4][4];
#pragma unroll
        for (int s = 0; s < 4; s++) {
            int j = min(jb + s * 32 + lane, NOx - 1);
            const float* wp = W2 + j;
#pragma unroll
            for (int u = 0; u < 4; u++) wv[s][u] = wp[(size_t)(k0 + u) * NOx];
        }
#pragma unroll
        for (int s = 0; s < 4; s++) {
            ull g[8];
#pragma unroll
            for (int p = 0; p < 8; p++) g[p] = gs[p * GHW + s * 32 + lane];
#pragma unroll
            for (int u = 0; u < 4; u++) {
                ull wpk = pack2(wv[s][u], wv[s][u]);
#pragma unroll
                for (int p = 0; p < 8; p++) acc[u][p] = ffma2(g[p], wpk, acc[u][p]);
            }
        }
    }
#pragma unroll
    for (int u = 0; u < 4; u++)
#pragma unroll
        for (int p = 0; p < 8; p++) {
            float x, y;
            unpack2(acc[u][p], x, y);
#pragma unroll
            for (int off = 16; off > 0; off >>= 1) {
                x += __shfl_xor_sync(0xFFFFFFFFu, x, off);
                y += __shfl_xor_sync(0xFFFFFFFFu, y, off);
            }
            if (lane == 0) {
                atomicAdd(&d_ghid[(2 * p) * Hx + k0 + u], x);
                atomicAdd(&d_ghid[(2 * p + 1) * Hx + k0 + u], y);
            }
        }
}

// ---------------- code_grad = (g_h * relu') @ W1^T ----------------
__global__ void __launch_bounds__(256) k_cgrad(float* __restrict__ out) {
    __shared__ float mg[128];
    int b = blockIdx.x, hg = blockIdx.y, t = threadIdx.x;
    if (t < 128) {
        int h = hg * 128 + t;
        mg[t] = d_ghid[b * Hx + h] * (d_h[h * Bx + b] > 0.f ? 1.f : 0.f);
    }
    __syncthreads();
    float acc = 0.f;
#pragma unroll 8
    for (int hh = 0; hh < 128; hh++) acc += mg[hh] * d_w1t[(hg * 128 + hh) * Lx + t];
    atomicAdd(&out[Bx + b * Lx + t], acc);
}

// ---------------- launch ----------------
extern "C" void kernel_launch(void* const* d_in, const int* in_sizes, int n_in,
                              void* d_out, int out_size) {
    const float* code = (const float*)d_in[0];
    const float* W1   = (const float*)d_in[1];
    const float* b1   = (const float*)d_in[2];
    const float* W2   = (const float*)d_in[3];
    const float* b2   = (const float*)d_in[4];
    const float* xyz  = (const float*)d_in[5];
    const float* wmat = (const float*)d_in[6];
    const float* area = (const float*)d_in[7];
    const int*   nbr  = (const int*)d_in[8];
    const int*   nnb  = (const int*)d_in[9];
    float* out = (float*)d_out;

    k_prep<<<(Bx * Nx * 4 + 255) / 256, 256>>>(W1, xyz, out);
    k_hidden<<<Hx / 256, 256>>>(code, W1, b1);
    k_recon<<<dim3((NQ + 255) / 256, 4), 256>>>(W2);
    k_comb<<<(Bx * Nx + 255) / 256, 256>>>(b2);
    k_rot<<<dim3((Nx + 255) / 256, Bx), 256>>>(wmat, nbr, nnb);
    k_grad<<<dim3((Nx + 255) / 256, Bx), 256>>>(wmat, area, nbr, nnb, out);
    k_gh<<<dim3(32, 16), 256>>>(W2);
    k_cgrad<<<dim3(Bx, 8), 256>>>(out);
    (void)in_sizes; (void)n_in; (void)out_size;
}

// round 11
// speedup vs baseline: 1.5736x; 1.0510x over previous
#include <cuda_runtime.h>

#define Bx 16
#define Nx 20000
#define Kx 16
#define Lx 256
#define Hx 1024
#define NOx 60000
#define NQ (NOx / 4)   // 15000 float4 per W2 row

typedef unsigned long long ull;

// ---------------- device scratch ----------------
__device__ float d_h[Hx * Bx];                 // hidden post-relu, [k*16+b]
__device__ float d_rpart[4 * Bx * Nx * 4];     // recon partials [ky][b][n][4]
__device__ float d_xr[Bx * Nx * 8];            // packed {x,y,z,0, rx,ry,rz,0} per (b,n)
__device__ float d_gflat[Bx * Nx * 4];         // grad wrt recon [b][n][4]
__device__ float d_ghid[Bx * Hx];              // [b][k]
__device__ float d_w1t[Hx * Lx];               // W1^T [h][l]

// ---------------- packed f32x2 helpers ----------------
static __device__ __forceinline__ ull pack2(float x, float y) {
    ull r;
    asm("mov.b64 %0,{%1,%2};" : "=l"(r) : "r"(__float_as_uint(x)), "r"(__float_as_uint(y)));
    return r;
}
static __device__ __forceinline__ void unpack2(ull v, float& x, float& y) {
    unsigned lo, hi;
    asm("mov.b64 {%0,%1},%2;" : "=r"(lo), "=r"(hi) : "l"(v));
    x = __uint_as_float(lo); y = __uint_as_float(hi);
}
static __device__ __forceinline__ ull ffma2(ull a, ull b, ull c) {
    ull d;
    asm("fma.rn.f32x2 %0,%1,%2,%3;" : "=l"(d) : "l"(a), "l"(b), "l"(c));
    return d;
}

// ---------------- prep: zero scratch, transpose W1, pack xyz, zero out ----------------
__global__ void k_prep(const float* __restrict__ W1, const float* __restrict__ xyz,
                       float* __restrict__ out) {
    int i = blockIdx.x * 256 + threadIdx.x;
    if (i < Bx * Nx * 4) d_gflat[i] = 0.f;
    if (i < Bx * Nx) {
        float4 v;
        v.x = xyz[i * 3 + 0]; v.y = xyz[i * 3 + 1]; v.z = xyz[i * 3 + 2]; v.w = 0.f;
        ((float4*)d_xr)[i * 2] = v;
    }
    if (i < Lx * Hx) { int l = i >> 10, h = i & 1023; d_w1t[h * Lx + l] = W1[i]; }
    if (i < Bx * Hx) d_ghid[i] = 0.f;
    if (i < Bx + Bx * Lx) out[i] = 0.f;
}

// ---------------- h = relu(code @ W1 + b1), stored [k][b] ----------------
__global__ void __launch_bounds__(256) k_hidden(const float* __restrict__ code,
                                                const float* __restrict__ W1,
                                                const float* __restrict__ b1) {
    __shared__ float cs[Bx * Lx];
    int t = threadIdx.x;
    for (int i = t; i < Bx * Lx; i += 256) cs[i] = code[i];
    __syncthreads();
    int j = blockIdx.x * 256 + t;
    float acc[Bx];
    float bj = b1[j];
#pragma unroll
    for (int b = 0; b < Bx; b++) acc[b] = bj;
#pragma unroll 8
    for (int l = 0; l < Lx; l++) {
        float w = W1[l * Hx + j];
#pragma unroll
        for (int b = 0; b < Bx; b++) acc[b] += cs[b * Lx + l] * w;
    }
#pragma unroll
    for (int b = 0; b < Bx; b++) d_h[j * Bx + b] = fmaxf(acc[b], 0.f);
}

// ---------------- recon partials: thread owns 4 consecutive j (LDG.128 of W2) ----------------
__global__ void __launch_bounds__(256, 2) k_recon(const float* __restrict__ W2) {
    __shared__ __align__(16) float hs[256 * 16];  // 16 KB h chunk [k][b]
    int t = threadIdx.x;
    int ky = blockIdx.y;
    for (int i = t; i < 256 * 16; i += 256) hs[i] = d_h[ky * 256 * 16 + i];
    __syncthreads();
    int q = blockIdx.x * 256 + t;           // float4 column index
    int qc = min(q, NQ - 1);
    const float4* wq = (const float4*)(W2 + (size_t)ky * 256 * NOx);
    const ulonglong2* hu = (const ulonglong2*)hs;
    ull acc[4][8];
#pragma unroll
    for (int jj = 0; jj < 4; jj++)
#pragma unroll
        for (int p = 0; p < 8; p++) acc[jj][p] = 0ull;

    for (int k4 = 0; k4 < 256; k4 += 4) {
        float4 w[4];
#pragma unroll
        for (int u = 0; u < 4; u++) w[u] = wq[(size_t)(k4 + u) * NQ + qc];
#pragma unroll
        for (int u = 0; u < 4; u++) {
            int k = k4 + u;
            ulonglong2 ha = hu[k * 4 + 0], hb = hu[k * 4 + 1];
            ulonglong2 hc = hu[k * 4 + 2], hd = hu[k * 4 + 3];
            ull hv[8] = {ha.x, ha.y, hb.x, hb.y, hc.x, hc.y, hd.x, hd.y};
            ull w0 = pack2(w[u].x, w[u].x), w1 = pack2(w[u].y, w[u].y);
            ull w2v = pack2(w[u].z, w[u].z), w3 = pack2(w[u].w, w[u].w);
#pragma unroll
            for (int p = 0; p < 8; p++) {
                acc[0][p] = ffma2(hv[p], w0, acc[0][p]);
                acc[1][p] = ffma2(hv[p], w1, acc[1][p]);
                acc[2][p] = ffma2(hv[p], w2v, acc[2][p]);
                acc[3][p] = ffma2(hv[p], w3, acc[3][p]);
            }
        }
    }
    if (q < NQ) {
#pragma unroll
        for (int jj = 0; jj < 4; jj++) {
            int j = 4 * q + jj;
            int n = j / 3, c = j - 3 * n;
            float* dst = d_rpart + ((size_t)ky * Bx * Nx + n) * 4 + c;
#pragma unroll
            for (int p = 0; p < 8; p++) {
                float x, y;
                unpack2(acc[jj][p], x, y);
                dst[(size_t)(2 * p) * Nx * 4] = x;
                dst[(size_t)(2 * p + 1) * Nx * 4] = y;
            }
        }
    }
}

// ---------------- combine partials + bias -> packed xr slots 4..7 ----------------
__global__ void k_comb(const float* __restrict__ b2) {
    int i = blockIdx.x * 256 + threadIdx.x;  // b*Nx + n
    if (i >= Bx * Nx) return;
    int n = i % Nx;
    float x = 0.f, y = 0.f, z = 0.f;
#pragma unroll
    for (int ky = 0; ky < 4; ky++) {
        const float* p = d_rpart + ((size_t)ky * Bx * Nx + i) * 4;
        x += p[0]; y += p[1]; z += p[2];
    }
    float4 r;
    r.x = x + b2[n * 3 + 0];
    r.y = y + b2[n * 3 + 1];
    r.z = z + b2[n * 3 + 2];
    r.w = 0.f;
    ((float4*)d_xr)[i * 2 + 1] = r;
}

// ---------------- Jacobi rotation on symmetric 4x4, compile-time (P,Q) ----------------
template <int P, int Q>
static __device__ __forceinline__ void jrot(float a[4][4], float v[4][4]) {
    float apq = a[P][Q];
    if (apq != 0.f) {
        float theta = 0.5f * (a[Q][Q] - a[P][P]) / apq;
        float tt = copysignf(1.f, theta) / (fabsf(theta) + sqrtf(theta * theta + 1.f));
        float c = rsqrtf(tt * tt + 1.f);
        float s = tt * c;
        a[P][P] -= tt * apq;
        a[Q][Q] += tt * apq;
        a[P][Q] = 0.f; a[Q][P] = 0.f;
#pragma unroll
        for (int r = 0; r < 4; r++) {
            if (r == P || r == Q) continue;
            float arp = a[r][P], arq = a[r][Q];
            float nrp = c * arp - s * arq;
            float nrq = s * arp + c * arq;
            a[r][P] = nrp; a[P][r] = nrp;
            a[r][Q] = nrq; a[Q][r] = nrq;
        }
#pragma unroll
        for (int r = 0; r < 4; r++) {
            float vrp = v[r][P], vrq = v[r][Q];
            v[r][P] = c * vrp - s * vrq;
            v[r][Q] = s * vrp + c * vrq;
        }
    }
}

// ---------------- fused per-vertex ARAP: S, rotation, energy, grad ----------------
__global__ void __launch_bounds__(128, 4) k_arap(const float* __restrict__ wmat,
                                                 const float* __restrict__ area,
                                                 const int* __restrict__ nbr,
                                                 const int* __restrict__ numnb,
                                                 float* __restrict__ out) {
    __shared__ float sh[96 * 128];  // [slot][tid]: 6 floats per nbr, 16 nbrs = 48 KB
    const float invNK = 1.f / (float)(Nx * Kx);
    int t = threadIdx.x;
    int n = blockIdx.x * 128 + t;
    int b = blockIdx.y;
    float ev = 0.f;
    if (n < Nx) {
        const float4* xr = ((const float4*)d_xr) + (size_t)b * Nx * 2;
        float4 xn = xr[2 * n], rn = xr[2 * n + 1];
        int nn = numnb[n];
        const int4* nb4 = (const int4*)(nbr + n * Kx);
        const float4* wm4 = (const float4*)(wmat + n * Kx);
        int jk[Kx]; float wk[Kx];
#pragma unroll
        for (int q = 0; q < 4; q++) {
            int4 jv = nb4[q]; float4 wv = wm4[q];
            jk[q * 4 + 0] = jv.x; jk[q * 4 + 1] = jv.y; jk[q * 4 + 2] = jv.z; jk[q * 4 + 3] = jv.w;
            wk[q * 4 + 0] = (q * 4 + 0 < nn) ? wv.x : 0.f;
            wk[q * 4 + 1] = (q * 4 + 1 < nn) ? wv.y : 0.f;
            wk[q * 4 + 2] = (q * 4 + 2 < nn) ? wv.z : 0.f;
            wk[q * 4 + 3] = (q * 4 + 3 < nn) ? wv.w : 0.f;
        }
        float S00 = 0, S01 = 0, S02 = 0, S10 = 0, S11 = 0, S12 = 0, S20 = 0, S21 = 0, S22 = 0;
#pragma unroll
        for (int k = 0; k < Kx; k++) {
            int j = jk[k]; float w = wk[k];
            float4 xj = xr[2 * j], rj = xr[2 * j + 1];   // same 128B line
            float dx = xn.x - xj.x, dy = xn.y - xj.y, dz = xn.z - xj.z;
            float cx = rn.x - rj.x, cy = rn.y - rj.y, cz = rn.z - rj.z;
            sh[(k * 6 + 0) * 128 + t] = dx; sh[(k * 6 + 1) * 128 + t] = dy; sh[(k * 6 + 2) * 128 + t] = dz;
            sh[(k * 6 + 3) * 128 + t] = cx; sh[(k * 6 + 4) * 128 + t] = cy; sh[(k * 6 + 5) * 128 + t] = cz;
            S00 += w * dx * cx; S01 += w * dx * cy; S02 += w * dx * cz;
            S10 += w * dy * cx; S11 += w * dy * cy; S12 += w * dy * cz;
            S20 += w * dz * cx; S21 += w * dz * cy; S22 += w * dz * cz;
        }
        // Davenport/Horn 4x4: max eigenvector = quaternion of best-fit R (d -> c)
        float a[4][4], v[4][4];
        a[0][0] = S00 + S11 + S22;
        a[1][1] = S00 - S11 - S22;
        a[2][2] = S11 - S00 - S22;
        a[3][3] = S22 - S00 - S11;
        a[0][1] = a[1][0] = S12 - S21;
        a[0][2] = a[2][0] = S20 - S02;
        a[0][3] = a[3][0] = S01 - S10;
        a[1][2] = a[2][1] = S01 + S10;
        a[1][3] = a[3][1] = S02 + S20;
        a[2][3] = a[3][2] = S12 + S21;
#pragma unroll
        for (int i = 0; i < 4; i++)
#pragma unroll
            for (int j2 = 0; j2 < 4; j2++) v[i][j2] = (i == j2) ? 1.f : 0.f;
#pragma unroll
        for (int sw = 0; sw < 6; sw++) {
            jrot<0, 1>(a, v); jrot<0, 2>(a, v); jrot<0, 3>(a, v);
            jrot<1, 2>(a, v); jrot<1, 3>(a, v); jrot<2, 3>(a, v);
        }
        float best = a[0][0];
        float qw = v[0][0], qx = v[1][0], qy = v[2][0], qz = v[3][0];
#pragma unroll
        for (int m = 1; m < 4; m++)
            if (a[m][m] > best) {
                best = a[m][m];
                qw = v[0][m]; qx = v[1][m]; qy = v[2][m]; qz = v[3][m];
            }
        float inv = rsqrtf(qw * qw + qx * qx + qy * qy + qz * qz);
        qw *= inv; qx *= inv; qy *= inv; qz *= inv;
        float R00 = 1.f - 2.f * (qy * qy + qz * qz);
        float R01 = 2.f * (qx * qy - qw * qz);
        float R02 = 2.f * (qx * qz + qw * qy);
        float R10 = 2.f * (qx * qy + qw * qz);
        float R11 = 1.f - 2.f * (qx * qx + qz * qz);
        float R12 = 2.f * (qy * qz - qw * qx);
        float R20 = 2.f * (qx * qz - qw * qy);
        float R21 = 2.f * (qy * qz + qw * qx);
        float R22 = 1.f - 2.f * (qx * qx + qy * qy);

        float an = area[n];
        float coef = 2.f * an * invNK;
        float gx = 0.f, gy = 0.f, gz = 0.f, es = 0.f;
        float4* gb4 = ((float4*)d_gflat) + (size_t)b * Nx;
#pragma unroll
        for (int k = 0; k < Kx; k++) {
            float dx = sh[(k * 6 + 0) * 128 + t], dy = sh[(k * 6 + 1) * 128 + t], dz = sh[(k * 6 + 2) * 128 + t];
            float cx = sh[(k * 6 + 3) * 128 + t], cy = sh[(k * 6 + 4) * 128 + t], cz = sh[(k * 6 + 5) * 128 + t];
            float r0 = cx - (R00 * dx + R01 * dy + R02 * dz);
            float r1 = cy - (R10 * dx + R11 * dy + R12 * dz);
            float r2 = cz - (R20 * dx + R21 * dy + R22 * dz);
            float w = wk[k];
            es += w * (r0 * r0 + r1 * r1 + r2 * r2);
            if (w != 0.f) {
                float g0 = coef * w * r0, g1 = coef * w * r1, g2 = coef * w * r2;
                gx += g0; gy += g1; gz += g2;
                atomicAdd(&gb4[jk[k]], make_float4(-g0, -g1, -g2, 0.f));
            }
        }
        atomicAdd(&gb4[n], make_float4(gx, gy, gz, 0.f));
        ev = an * es;
    }
    __syncthreads();
    sh[t] = ev;
    __syncthreads();
    for (int s = 64; s > 0; s >>= 1) {
        if (t < s) sh[t] += sh[t + s];
        __syncthreads();
    }
    if (t == 0) atomicAdd(&out[b], sh[0] * invNK);
}

// ---------------- g_h = g_flat @ W2^T (streams W2 again) ----------------
#define GHW 128
__global__ void __launch_bounds__(256, 2) k_gh(const float* __restrict__ W2) {
    __shared__ ull gs[8 * GHW];  // [p][jwin], 8 KB, conflict-free
    int t = threadIdx.x;
    int lane = t & 31, wrp = t >> 5;
    int k0 = blockIdx.x * 32 + wrp * 4;
    ull acc[4][8];
#pragma unroll
    for (int u = 0; u < 4; u++)
#pragma unroll
        for (int p = 0; p < 8; p++) acc[u][p] = 0ull;

    for (int jb = blockIdx.y * GHW; jb < NOx; jb += gridDim.y * GHW) {
        __syncthreads();
        for (int idx = t; idx < 8 * GHW; idx += 256) {
            int p = idx >> 7, jj = idx & (GHW - 1);
            int j = jb + jj;
            float v0 = 0.f, v1 = 0.f;
            if (j < NOx) {
                int n = j / 3, c = j - 3 * n;
                v0 = d_gflat[((size_t)(2 * p) * Nx + n) * 4 + c];
                v1 = d_gflat[((size_t)(2 * p + 1) * Nx + n) * 4 + c];
            }
            gs[idx] = pack2(v0, v1);
        }
        __syncthreads();
        float wv[4][4];
#pragma unroll
        for (int s = 0; s < 4; s++) {
            int j = min(jb + s * 32 + lane, NOx - 1);
            const float* wp = W2 + j;
#pragma unroll
            for (int u = 0; u < 4; u++) wv[s][u] = wp[(size_t)(k0 + u) * NOx];
        }
#pragma unroll
        for (int s = 0; s < 4; s++) {
            ull g[8];
#pragma unroll
            for (int p = 0; p < 8; p++) g[p] = gs[p * GHW + s * 32 + lane];
#pragma unroll
            for (int u = 0; u < 4; u++) {
                ull wpk = pack2(wv[s][u], wv[s][u]);
#pragma unroll
                for (int p = 0; p < 8; p++) acc[u][p] = ffma2(g[p], wpk, acc[u][p]);
            }
        }
    }
#pragma unroll
    for (int u = 0; u < 4; u++)
#pragma unroll
        for (int p = 0; p < 8; p++) {
            float x, y;
            unpack2(acc[u][p], x, y);
#pragma unroll
            for (int off = 16; off > 0; off >>= 1) {
                x += __shfl_xor_sync(0xFFFFFFFFu, x, off);
                y += __shfl_xor_sync(0xFFFFFFFFu, y, off);
            }
            if (lane == 0) {
                atomicAdd(&d_ghid[(2 * p) * Hx + k0 + u], x);
                atomicAdd(&d_ghid[(2 * p + 1) * Hx + k0 + u], y);
            }
        }
}

// ---------------- code_grad = (g_h * relu') @ W1^T ----------------
__global__ void __launch_bounds__(256) k_cgrad(float* __restrict__ out) {
    __shared__ float mg[128];
    int b = blockIdx.x, hg = blockIdx.y, t = threadIdx.x;
    if (t < 128) {
        int h = hg * 128 + t;
        mg[t] = d_ghid[b * Hx + h] * (d_h[h * Bx + b] > 0.f ? 1.f : 0.f);
    }
    __syncthreads();
    float acc = 0.f;
#pragma unroll 8
    for (int hh = 0; hh < 128; hh++) acc += mg[hh] * d_w1t[(hg * 128 + hh) * Lx + t];
    atomicAdd(&out[Bx + b * Lx + t], acc);
}

// ---------------- launch ----------------
extern "C" void kernel_launch(void* const* d_in, const int* in_sizes, int n_in,
                              void* d_out, int out_size) {
    const float* code = (const float*)d_in[0];
    const float* W1   = (const float*)d_in[1];
    const float* b1   = (const float*)d_in[2];
    const float* W2   = (const float*)d_in[3];
    const float* b2   = (const float*)d_in[4];
    const float* xyz  = (const float*)d_in[5];
    const float* wmat = (const float*)d_in[6];
    const float* area = (const float*)d_in[7];
    const int*   nbr  = (const int*)d_in[8];
    const int*   nnb  = (const int*)d_in[9];
    float* out = (float*)d_out;

    k_prep<<<(Bx * Nx * 4 + 255) / 256, 256>>>(W1, xyz, out);
    k_hidden<<<Hx / 256, 256>>>(code, W1, b1);
    k_recon<<<dim3((NQ + 255) / 256, 4), 256>>>(W2);
    k_comb<<<(Bx * Nx + 255) / 256, 256>>>(b2);
    k_arap<<<dim3((Nx + 127) / 128, Bx), 128>>>(wmat, area, nbr, nnb, out);
    k_gh<<<dim3(32, 16), 256>>>(W2);
    k_cgrad<<<dim3(Bx, 8), 256>>>(out);
    (void)in_sizes; (void)n_in; (void)out_size;
}

// round 12
// speedup vs baseline: 1.7308x; 1.0999x over previous
#include <cuda_runtime.h>

#define Bx 16
#define Nx 20000
#define Kx 16
#define Lx 256
#define Hx 1024
#define NOx 60000
#define NQ (NOx / 4)   // 15000 float4 per W2 row

typedef unsigned long long ull;

// ---------------- device scratch ----------------
__device__ float d_h[Hx * Bx];                 // hidden post-relu, [k*16+b]
__device__ float d_rflat[4 * Bx * NOx];        // recon partials [ky][b][j]  (15.4 MB)
__device__ float d_xr[Bx * Nx * 8];            // packed {x,y,z,0, rx,ry,rz,0} per (b,n)
__device__ float d_gflat[Bx * Nx * 4];         // grad wrt recon [b][n][4]
__device__ float d_ghid[Bx * Hx];              // [b][k]
__device__ float d_w1t[Hx * Lx];               // W1^T [h][l]

// ---------------- packed f32x2 helpers ----------------
static __device__ __forceinline__ ull pack2(float x, float y) {
    ull r;
    asm("mov.b64 %0,{%1,%2};" : "=l"(r) : "r"(__float_as_uint(x)), "r"(__float_as_uint(y)));
    return r;
}
static __device__ __forceinline__ void unpack2(ull v, float& x, float& y) {
    unsigned lo, hi;
    asm("mov.b64 {%0,%1},%2;" : "=r"(lo), "=r"(hi) : "l"(v));
    x = __uint_as_float(lo); y = __uint_as_float(hi);
}
static __device__ __forceinline__ ull ffma2(ull a, ull b, ull c) {
    ull d;
    asm("fma.rn.f32x2 %0,%1,%2,%3;" : "=l"(d) : "l"(a), "l"(b), "l"(c));
    return d;
}

// ---------------- prep + hidden fused (blocks 0..3 = hidden GEMM) ----------------
__global__ void __launch_bounds__(256) k_prephid(const float* __restrict__ code,
                                                 const float* __restrict__ W1,
                                                 const float* __restrict__ b1,
                                                 const float* __restrict__ xyz,
                                                 float* __restrict__ out) {
    int t = threadIdx.x;
    if (blockIdx.x < 4) {
        // hidden: h = relu(code @ W1 + b1), stored [k][b]
        __shared__ float cs[Bx * Lx];
        for (int i = t; i < Bx * Lx; i += 256) cs[i] = code[i];
        __syncthreads();
        int j = blockIdx.x * 256 + t;
        float acc[Bx];
        float bj = b1[j];
#pragma unroll
        for (int b = 0; b < Bx; b++) acc[b] = bj;
#pragma unroll 8
        for (int l = 0; l < Lx; l++) {
            float w = W1[l * Hx + j];
#pragma unroll
            for (int b = 0; b < Bx; b++) acc[b] += cs[b * Lx + l] * w;
        }
#pragma unroll
        for (int b = 0; b < Bx; b++) d_h[j * Bx + b] = fmaxf(acc[b], 0.f);
        return;
    }
    int i = (blockIdx.x - 4) * 256 + t;
    if (i < Bx * Nx * 4) d_gflat[i] = 0.f;
    if (i < Bx * Nx) {
        float4 v;
        v.x = xyz[i * 3 + 0]; v.y = xyz[i * 3 + 1]; v.z = xyz[i * 3 + 2]; v.w = 0.f;
        ((float4*)d_xr)[i * 2] = v;
    }
    if (i < Lx * Hx) { int l = i >> 10, h = i & 1023; d_w1t[h * Lx + l] = W1[i]; }
    if (i < Bx * Hx) d_ghid[i] = 0.f;
    if (i < Bx + Bx * Lx) out[i] = 0.f;
}

// ---------------- recon partials: thread owns 4 consecutive j; coalesced flat stores ----------------
__global__ void __launch_bounds__(256, 2) k_recon(const float* __restrict__ W2) {
    __shared__ __align__(16) float hs[256 * 16];  // 16 KB h chunk [k][b]
    int t = threadIdx.x;
    int ky = blockIdx.y;
    for (int i = t; i < 256 * 16; i += 256) hs[i] = d_h[ky * 256 * 16 + i];
    __syncthreads();
    int q = blockIdx.x * 256 + t;           // float4 column index
    int qc = min(q, NQ - 1);
    const float4* wq = (const float4*)(W2 + (size_t)ky * 256 * NOx);
    const ulonglong2* hu = (const ulonglong2*)hs;
    ull acc[4][8];
#pragma unroll
    for (int jj = 0; jj < 4; jj++)
#pragma unroll
        for (int p = 0; p < 8; p++) acc[jj][p] = 0ull;

    for (int k4 = 0; k4 < 256; k4 += 4) {
        float4 w[4];
#pragma unroll
        for (int u = 0; u < 4; u++) w[u] = wq[(size_t)(k4 + u) * NQ + qc];
#pragma unroll
        for (int u = 0; u < 4; u++) {
            int k = k4 + u;
            ulonglong2 ha = hu[k * 4 + 0], hb = hu[k * 4 + 1];
            ulonglong2 hc = hu[k * 4 + 2], hd = hu[k * 4 + 3];
            ull hv[8] = {ha.x, ha.y, hb.x, hb.y, hc.x, hc.y, hd.x, hd.y};
            ull w0 = pack2(w[u].x, w[u].x), w1 = pack2(w[u].y, w[u].y);
            ull w2v = pack2(w[u].z, w[u].z), w3 = pack2(w[u].w, w[u].w);
#pragma unroll
            for (int p = 0; p < 8; p++) {
                acc[0][p] = ffma2(hv[p], w0, acc[0][p]);
                acc[1][p] = ffma2(hv[p], w1, acc[1][p]);
                acc[2][p] = ffma2(hv[p], w2v, acc[2][p]);
                acc[3][p] = ffma2(hv[p], w3, acc[3][p]);
            }
        }
    }
    if (q < NQ) {
        float* base = d_rflat + (size_t)ky * Bx * NOx + 4 * q;
#pragma unroll
        for (int p = 0; p < 8; p++) {
            float x0, y0, x1, y1, x2, y2, x3, y3;
            unpack2(acc[0][p], x0, y0);
            unpack2(acc[1][p], x1, y1);
            unpack2(acc[2][p], x2, y2);
            unpack2(acc[3][p], x3, y3);
            *(float4*)(base + (size_t)(2 * p) * NOx)     = make_float4(x0, x1, x2, x3);
            *(float4*)(base + (size_t)(2 * p + 1) * NOx) = make_float4(y0, y1, y2, y3);
        }
    }
}

// ---------------- combine flat partials + bias -> packed xr slots 4..7 ----------------
__global__ void k_comb(const float* __restrict__ b2) {
    int i = blockIdx.x * 256 + threadIdx.x;  // b*Nx + n
    if (i >= Bx * Nx) return;
    int b = i / Nx, n = i - b * Nx;
    float x = 0.f, y = 0.f, z = 0.f;
#pragma unroll
    for (int ky = 0; ky < 4; ky++) {
        const float* p = d_rflat + (size_t)(ky * Bx + b) * NOx + 3 * n;
        x += p[0]; y += p[1]; z += p[2];
    }
    float4 r;
    r.x = x + b2[n * 3 + 0];
    r.y = y + b2[n * 3 + 1];
    r.z = z + b2[n * 3 + 2];
    r.w = 0.f;
    ((float4*)d_xr)[i * 2 + 1] = r;
}

// ---------------- Jacobi rotation on symmetric 4x4, compile-time (P,Q) ----------------
template <int P, int Q>
static __device__ __forceinline__ void jrot(float a[4][4], float v[4][4]) {
    float apq = a[P][Q];
    if (apq != 0.f) {
        float theta = __fdividef(0.5f * (a[Q][Q] - a[P][P]), apq);
        float tt = __fdividef(copysignf(1.f, theta), fabsf(theta) + sqrtf(theta * theta + 1.f));
        float c = rsqrtf(tt * tt + 1.f);
        float s = tt * c;
        a[P][P] -= tt * apq;
        a[Q][Q] += tt * apq;
        a[P][Q] = 0.f; a[Q][P] = 0.f;
#pragma unroll
        for (int r = 0; r < 4; r++) {
            if (r == P || r == Q) continue;
            float arp = a[r][P], arq = a[r][Q];
            float nrp = c * arp - s * arq;
            float nrq = s * arp + c * arq;
            a[r][P] = nrp; a[P][r] = nrp;
            a[r][Q] = nrq; a[Q][r] = nrq;
        }
#pragma unroll
        for (int r = 0; r < 4; r++) {
            float vrp = v[r][P], vrq = v[r][Q];
            v[r][P] = c * vrp - s * vrq;
            v[r][Q] = s * vrp + c * vrq;
        }
    }
}

// ---------------- fused per-vertex ARAP: S, rotation, energy, grad ----------------
__global__ void __launch_bounds__(128, 4) k_arap(const float* __restrict__ wmat,
                                                 const float* __restrict__ area,
                                                 const int* __restrict__ nbr,
                                                 const int* __restrict__ numnb,
                                                 float* __restrict__ out) {
    __shared__ float sh[96 * 128];  // [slot][tid]: 6 floats per nbr, 16 nbrs = 48 KB
    const float invNK = 1.f / (float)(Nx * Kx);
    int t = threadIdx.x;
    int n = blockIdx.x * 128 + t;
    int b = blockIdx.y;
    float ev = 0.f;
    if (n < Nx) {
        const float4* xr = ((const float4*)d_xr) + (size_t)b * Nx * 2;
        float4 xn = xr[2 * n], rn = xr[2 * n + 1];
        int nn = numnb[n];
        const int4* nb4 = (const int4*)(nbr + n * Kx);
        const float4* wm4 = (const float4*)(wmat + n * Kx);
        int jk[Kx]; float wk[Kx];
#pragma unroll
        for (int q = 0; q < 4; q++) {
            int4 jv = nb4[q]; float4 wv = wm4[q];
            jk[q * 4 + 0] = jv.x; jk[q * 4 + 1] = jv.y; jk[q * 4 + 2] = jv.z; jk[q * 4 + 3] = jv.w;
            wk[q * 4 + 0] = (q * 4 + 0 < nn) ? wv.x : 0.f;
            wk[q * 4 + 1] = (q * 4 + 1 < nn) ? wv.y : 0.f;
            wk[q * 4 + 2] = (q * 4 + 2 < nn) ? wv.z : 0.f;
            wk[q * 4 + 3] = (q * 4 + 3 < nn) ? wv.w : 0.f;
        }
        float S00 = 0, S01 = 0, S02 = 0, S10 = 0, S11 = 0, S12 = 0, S20 = 0, S21 = 0, S22 = 0;
#pragma unroll
        for (int k = 0; k < Kx; k++) {
            int j = jk[k]; float w = wk[k];
            float4 xj = xr[2 * j], rj = xr[2 * j + 1];   // same 32B sector
            float dx = xn.x - xj.x, dy = xn.y - xj.y, dz = xn.z - xj.z;
            float cx = rn.x - rj.x, cy = rn.y - rj.y, cz = rn.z - rj.z;
            sh[(k * 6 + 0) * 128 + t] = dx; sh[(k * 6 + 1) * 128 + t] = dy; sh[(k * 6 + 2) * 128 + t] = dz;
            sh[(k * 6 + 3) * 128 + t] = cx; sh[(k * 6 + 4) * 128 + t] = cy; sh[(k * 6 + 5) * 128 + t] = cz;
            S00 += w * dx * cx; S01 += w * dx * cy; S02 += w * dx * cz;
            S10 += w * dy * cx; S11 += w * dy * cy; S12 += w * dy * cz;
            S20 += w * dz * cx; S21 += w * dz * cy; S22 += w * dz * cz;
        }
        // Davenport/Horn 4x4: max eigenvector = quaternion of best-fit R (d -> c)
        float a[4][4], v[4][4];
        a[0][0] = S00 + S11 + S22;
        a[1][1] = S00 - S11 - S22;
        a[2][2] = S11 - S00 - S22;
        a[3][3] = S22 - S00 - S11;
        a[0][1] = a[1][0] = S12 - S21;
        a[0][2] = a[2][0] = S20 - S02;
        a[0][3] = a[3][0] = S01 - S10;
        a[1][2] = a[2][1] = S01 + S10;
        a[1][3] = a[3][1] = S02 + S20;
        a[2][3] = a[3][2] = S12 + S21;
#pragma unroll
        for (int i = 0; i < 4; i++)
#pragma unroll
            for (int j2 = 0; j2 < 4; j2++) v[i][j2] = (i == j2) ? 1.f : 0.f;
#pragma unroll
        for (int sw = 0; sw < 4; sw++) {
            jrot<0, 1>(a, v); jrot<0, 2>(a, v); jrot<0, 3>(a, v);
            jrot<1, 2>(a, v); jrot<1, 3>(a, v); jrot<2, 3>(a, v);
        }
        float best = a[0][0];
        float qw = v[0][0], qx = v[1][0], qy = v[2][0], qz = v[3][0];
#pragma unroll
        for (int m = 1; m < 4; m++)
            if (a[m][m] > best) {
                best = a[m][m];
                qw = v[0][m]; qx = v[1][m]; qy = v[2][m]; qz = v[3][m];
            }
        float inv = rsqrtf(qw * qw + qx * qx + qy * qy + qz * qz);
        qw *= inv; qx *= inv; qy *= inv; qz *= inv;
        float R00 = 1.f - 2.f * (qy * qy + qz * qz);
        float R01 = 2.f * (qx * qy - qw * qz);
        float R02 = 2.f * (qx * qz + qw * qy);
        float R10 = 2.f * (qx * qy + qw * qz);
        float R11 = 1.f - 2.f * (qx * qx + qz * qz);
        float R12 = 2.f * (qy * qz - qw * qx);
        float R20 = 2.f * (qx * qz - qw * qy);
        float R21 = 2.f * (qy * qz + qw * qx);
        float R22 = 1.f - 2.f * (qx * qx + qy * qy);

        float an = area[n];
        float coef = 2.f * an * invNK;
        float gx = 0.f, gy = 0.f, gz = 0.f, es = 0.f;
        float4* gb4 = ((float4*)d_gflat) + (size_t)b * Nx;
#pragma unroll
        for (int k = 0; k < Kx; k++) {
            float dx = sh[(k * 6 + 0) * 128 + t], dy = sh[(k * 6 + 1) * 128 + t], dz = sh[(k * 6 + 2) * 128 + t];
            float cx = sh[(k * 6 + 3) * 128 + t], cy = sh[(k * 6 + 4) * 128 + t], cz = sh[(k * 6 + 5) * 128 + t];
            float r0 = cx - (R00 * dx + R01 * dy + R02 * dz);
            float r1 = cy - (R10 * dx + R11 * dy + R12 * dz);
            float r2 = cz - (R20 * dx + R21 * dy + R22 * dz);
            float w = wk[k];
            es += w * (r0 * r0 + r1 * r1 + r2 * r2);
            if (w != 0.f) {
                float g0 = coef * w * r0, g1 = coef * w * r1, g2 = coef * w * r2;
                gx += g0; gy += g1; gz += g2;
                atomicAdd(&gb4[jk[k]], make_float4(-g0, -g1, -g2, 0.f));
            }
        }
        atomicAdd(&gb4[n], make_float4(gx, gy, gz, 0.f));
        ev = an * es;
    }
    __syncthreads();
    sh[t] = ev;
    __syncthreads();
    for (int s = 64; s > 0; s >>= 1) {
        if (t < s) sh[t] += sh[t + s];
        __syncthreads();
    }
    if (t == 0) atomicAdd(&out[b], sh[0] * invNK);
}

// ---------------- g_h = g_flat @ W2^T (streams W2 again) ----------------
#define GHW 128
__global__ void __launch_bounds__(256, 2) k_gh(const float* __restrict__ W2) {
    __shared__ ull gs[8 * GHW];  // [p][jwin], 8 KB, conflict-free
    int t = threadIdx.x;
    int lane = t & 31, wrp = t >> 5;
    int k0 = blockIdx.x * 32 + wrp * 4;
    ull acc[4][8];
#pragma unroll
    for (int u = 0; u < 4; u++)
#pragma unroll
        for (int p = 0; p < 8; p++) acc[u][p] = 0ull;

    for (int jb = blockIdx.y * GHW; jb < NOx; jb += gridDim.y * GHW) {
        __syncthreads();
        for (int idx = t; idx < 8 * GHW; idx += 256) {
            int p = idx >> 7, jj = idx & (GHW - 1);
            int j = jb + jj;
            float v0 = 0.f, v1 = 0.f;
            if (j < NOx) {
                int n = j / 3, c = j - 3 * n;
                v0 = d_gflat[((size_t)(2 * p) * Nx + n) * 4 + c];
                v1 = d_gflat[((size_t)(2 * p + 1) * Nx + n) * 4 + c];
            }
            gs[idx] = pack2(v0, v1);
        }
        __syncthreads();
        float wv[4][4];
#pragma unroll
        for (int s = 0; s < 4; s++) {
            int j = min(jb + s * 32 + lane, NOx - 1);
            const float* wp = W2 + j;
#pragma unroll
            for (int u = 0; u < 4; u++) wv[s][u] = wp[(size_t)(k0 + u) * NOx];
        }
#pragma unroll
        for (int s = 0; s < 4; s++) {
            ull g[8];
#pragma unroll
            for (int p = 0; p < 8; p++) g[p] = gs[p * GHW + s * 32 + lane];
#pragma unroll
            for (int u = 0; u < 4; u++) {
                ull wpk = pack2(wv[s][u], wv[s][u]);
#pragma unroll
                for (int p = 0; p < 8; p++) acc[u][p] = ffma2(g[p], wpk, acc[u][p]);
            }
        }
    }
#pragma unroll
    for (int u = 0; u < 4; u++)
#pragma unroll
        for (int p = 0; p < 8; p++) {
            float x, y;
            unpack2(acc[u][p], x, y);
#pragma unroll
            for (int off = 16; off > 0; off >>= 1) {
                x += __shfl_xor_sync(0xFFFFFFFFu, x, off);
                y += __shfl_xor_sync(0xFFFFFFFFu, y, off);
            }
            if (lane == 0) {
                atomicAdd(&d_ghid[(2 * p) * Hx + k0 + u], x);
                atomicAdd(&d_ghid[(2 * p + 1) * Hx + k0 + u], y);
            }
        }
}

// ---------------- code_grad = (g_h * relu') @ W1^T ----------------
__global__ void __launch_bounds__(256) k_cgrad(float* __restrict__ out) {
    __shared__ float mg[128];
    int b = blockIdx.x, hg = blockIdx.y, t = threadIdx.x;
    if (t < 128) {
        int h = hg * 128 + t;
        mg[t] = d_ghid[b * Hx + h] * (d_h[h * Bx + b] > 0.f ? 1.f : 0.f);
    }
    __syncthreads();
    float acc = 0.f;
#pragma unroll 8
    for (int hh = 0; hh < 128; hh++) acc += mg[hh] * d_w1t[(hg * 128 + hh) * Lx + t];
    atomicAdd(&out[Bx + b * Lx + t], acc);
}

// ---------------- launch ----------------
extern "C" void kernel_launch(void* const* d_in, const int* in_sizes, int n_in,
                              void* d_out, int out_size) {
    const float* code = (const float*)d_in[0];
    const float* W1   = (const float*)d_in[1];
    const float* b1   = (const float*)d_in[2];
    const float* W2   = (const float*)d_in[3];
    const float* b2   = (const float*)d_in[4];
    const float* xyz  = (const float*)d_in[5];
    const float* wmat = (const float*)d_in[6];
    const float* area = (const float*)d_in[7];
    const int*   nbr  = (const int*)d_in[8];
    const int*   nnb  = (const int*)d_in[9];
    float* out = (float*)d_out;

    k_prephid<<<4 + (Bx * Nx * 4 + 255) / 256, 256>>>(code, W1, b1, xyz, out);
    k_recon<<<dim3((NQ + 255) / 256, 4), 256>>>(W2);
    k_comb<<<(Bx * Nx + 255) / 256, 256>>>(b2);
    k_arap<<<dim3((Nx + 127) / 128, Bx), 128>>>(wmat, area, nbr, nnb, out);
    k_gh<<<dim3(32, 16), 256>>>(W2);
    k_cgrad<<<dim3(Bx, 8), 256>>>(out);
    (void)in_sizes; (void)n_in; (void)out_size;
}

// round 13
// speedup vs baseline: 1.9615x; 1.1333x over previous
#include <cuda_runtime.h>

#define Bx 16
#define Nx 20000
#define Kx 16
#define Lx 256
#define Hx 1024
#define NOx 60000
#define NQ (NOx / 4)   // 15000 float4 per W2 row

typedef unsigned long long ull;

// ---------------- device scratch ----------------
__device__ float d_h[Hx * Bx];                 // hidden post-relu, [k*16+b]
__device__ float d_rflat[8 * Bx * NOx];        // recon partials [ky][b][j]  (30.7 MB)
__device__ float d_xr[Bx * Nx * 8];            // packed {x,y,z,0, rx,ry,rz,0} per (b,n)
__device__ float d_gflat[Bx * Nx * 4];         // grad wrt recon [b][n][4]
__device__ float d_ghid[Bx * Hx];              // [b][k]
__device__ float d_w1t[Hx * Lx];               // W1^T [h][l]

// ---------------- packed f32x2 helpers ----------------
static __device__ __forceinline__ ull pack2(float x, float y) {
    ull r;
    asm("mov.b64 %0,{%1,%2};" : "=l"(r) : "r"(__float_as_uint(x)), "r"(__float_as_uint(y)));
    return r;
}
static __device__ __forceinline__ void unpack2(ull v, float& x, float& y) {
    unsigned lo, hi;
    asm("mov.b64 {%0,%1},%2;" : "=r"(lo), "=r"(hi) : "l"(v));
    x = __uint_as_float(lo); y = __uint_as_float(hi);
}
static __device__ __forceinline__ ull ffma2(ull a, ull b, ull c) {
    ull d;
    asm("fma.rn.f32x2 %0,%1,%2,%3;" : "=l"(d) : "l"(a), "l"(b), "l"(c));
    return d;
}

// ---------------- prep part 1: zero gflat, pack xyz ----------------
__global__ void k_prep1(const float* __restrict__ xyz) {
    int i = blockIdx.x * 256 + threadIdx.x;
    if (i < Bx * Nx * 4) d_gflat[i] = 0.f;
    if (i < Bx * Nx) {
        float4 v;
        v.x = xyz[i * 3 + 0]; v.y = xyz[i * 3 + 1]; v.z = xyz[i * 3 + 2]; v.w = 0.f;
        ((float4*)d_xr)[i * 2] = v;
    }
}

// ---------------- prep part 2: W1 transpose, zero ghid/out ----------------
__global__ void k_prep2(const float* __restrict__ W1, float* __restrict__ out) {
    int i = blockIdx.x * 256 + threadIdx.x;
    if (i < Lx * Hx) { int l = i >> 10, h = i & 1023; d_w1t[h * Lx + l] = W1[i]; }
    if (i < Bx * Hx) d_ghid[i] = 0.f;
    if (i < Bx + Bx * Lx) out[i] = 0.f;
}

// ---------------- h = relu(code @ W1 + b1), stored [k][b] ----------------
__global__ void __launch_bounds__(256) k_hidden(const float* __restrict__ code,
                                                const float* __restrict__ W1,
                                                const float* __restrict__ b1) {
    __shared__ float cs[Bx * Lx];
    int t = threadIdx.x;
    for (int i = t; i < Bx * Lx; i += 256) cs[i] = code[i];
    __syncthreads();
    int j = blockIdx.x * 256 + t;
    float acc[Bx];
    float bj = b1[j];
#pragma unroll
    for (int b = 0; b < Bx; b++) acc[b] = bj;
#pragma unroll 8
    for (int l = 0; l < Lx; l++) {
        float w = W1[l * Hx + j];
#pragma unroll
        for (int b = 0; b < Bx; b++) acc[b] += cs[b * Lx + l] * w;
    }
#pragma unroll
    for (int b = 0; b < Bx; b++) d_h[j * Bx + b] = fmaxf(acc[b], 0.f);
}

// ---------------- recon partials: exact-1-wave grid (37,8), 2 q-passes/thread ----------------
__global__ void __launch_bounds__(256, 2) k_recon(const float* __restrict__ W2) {
    __shared__ __align__(16) float hs[128 * 16];  // 8 KB h chunk [k][b]
    int t = threadIdx.x;
    int ky = blockIdx.y;                          // 8 chunks of 128 k
    for (int i = t; i < 128 * 16; i += 256) hs[i] = d_h[ky * 128 * 16 + i];
    __syncthreads();
    const ulonglong2* hu = (const ulonglong2*)hs;
    const float4* wq = ((const float4*)W2) + (size_t)(ky * 128) * NQ;

#pragma unroll 1
    for (int pass = 0; pass < 2; pass++) {
        int q = blockIdx.x * 256 + t + pass * (37 * 256);
        int qc = min(q, NQ - 1);
        ull acc[4][8];
#pragma unroll
        for (int jj = 0; jj < 4; jj++)
#pragma unroll
            for (int p = 0; p < 8; p++) acc[jj][p] = 0ull;

        for (int k4 = 0; k4 < 128; k4 += 4) {
            float4 w[4];
#pragma unroll
            for (int u = 0; u < 4; u++) w[u] = wq[(size_t)(k4 + u) * NQ + qc];
#pragma unroll
            for (int u = 0; u < 4; u++) {
                int k = k4 + u;
                ulonglong2 ha = hu[k * 4 + 0], hb = hu[k * 4 + 1];
                ulonglong2 hc = hu[k * 4 + 2], hd = hu[k * 4 + 3];
                ull hv[8] = {ha.x, ha.y, hb.x, hb.y, hc.x, hc.y, hd.x, hd.y};
                ull w0 = pack2(w[u].x, w[u].x), w1 = pack2(w[u].y, w[u].y);
                ull w2v = pack2(w[u].z, w[u].z), w3 = pack2(w[u].w, w[u].w);
#pragma unroll
                for (int p = 0; p < 8; p++) {
                    acc[0][p] = ffma2(hv[p], w0, acc[0][p]);
                    acc[1][p] = ffma2(hv[p], w1, acc[1][p]);
                    acc[2][p] = ffma2(hv[p], w2v, acc[2][p]);
                    acc[3][p] = ffma2(hv[p], w3, acc[3][p]);
                }
            }
        }
        if (q < NQ) {
            float* base = d_rflat + (size_t)ky * Bx * NOx + 4 * q;
#pragma unroll
            for (int p = 0; p < 8; p++) {
                float x0, y0, x1, y1, x2, y2, x3, y3;
                unpack2(acc[0][p], x0, y0);
                unpack2(acc[1][p], x1, y1);
                unpack2(acc[2][p], x2, y2);
                unpack2(acc[3][p], x3, y3);
                *(float4*)(base + (size_t)(2 * p) * NOx)     = make_float4(x0, x1, x2, x3);
                *(float4*)(base + (size_t)(2 * p + 1) * NOx) = make_float4(y0, y1, y2, y3);
            }
        }
    }
}

// ---------------- combine flat partials + bias -> packed xr slots 4..7 ----------------
__global__ void k_comb(const float* __restrict__ b2) {
    int i = blockIdx.x * 256 + threadIdx.x;  // b*Nx + n
    if (i >= Bx * Nx) return;
    int b = i / Nx, n = i - b * Nx;
    float x = 0.f, y = 0.f, z = 0.f;
#pragma unroll
    for (int ky = 0; ky < 8; ky++) {
        const float* p = d_rflat + (size_t)(ky * Bx + b) * NOx + 3 * n;
        x += p[0]; y += p[1]; z += p[2];
    }
    float4 r;
    r.x = x + b2[n * 3 + 0];
    r.y = y + b2[n * 3 + 1];
    r.z = z + b2[n * 3 + 2];
    r.w = 0.f;
    ((float4*)d_xr)[i * 2 + 1] = r;
}

// ---------------- Jacobi rotation on symmetric 4x4, compile-time (P,Q) ----------------
template <int P, int Q>
static __device__ __forceinline__ void jrot(float a[4][4], float v[4][4]) {
    float apq = a[P][Q];
    if (apq != 0.f) {
        float theta = __fdividef(0.5f * (a[Q][Q] - a[P][P]), apq);
        float tt = __fdividef(copysignf(1.f, theta), fabsf(theta) + sqrtf(theta * theta + 1.f));
        float c = rsqrtf(tt * tt + 1.f);
        float s = tt * c;
        a[P][P] -= tt * apq;
        a[Q][Q] += tt * apq;
        a[P][Q] = 0.f; a[Q][P] = 0.f;
#pragma unroll
        for (int r = 0; r < 4; r++) {
            if (r == P || r == Q) continue;
            float arp = a[r][P], arq = a[r][Q];
            float nrp = c * arp - s * arq;
            float nrq = s * arp + c * arq;
            a[r][P] = nrp; a[P][r] = nrp;
            a[r][Q] = nrq; a[Q][r] = nrq;
        }
#pragma unroll
        for (int r = 0; r < 4; r++) {
            float vrp = v[r][P], vrq = v[r][Q];
            v[r][P] = c * vrp - s * vrq;
            v[r][Q] = s * vrp + c * vrq;
        }
    }
}

// ---------------- fused per-vertex ARAP: predicated on w!=0 ----------------
__global__ void __launch_bounds__(128, 4) k_arap(const float* __restrict__ wmat,
                                                 const float* __restrict__ area,
                                                 const int* __restrict__ nbr,
                                                 const int* __restrict__ numnb,
                                                 float* __restrict__ out) {
    __shared__ float sh[96 * 128];  // [slot][tid]: 6 floats per nbr, 16 nbrs = 48 KB
    const float invNK = 1.f / (float)(Nx * Kx);
    int t = threadIdx.x;
    int n = blockIdx.x * 128 + t;
    int b = blockIdx.y;
    float ev = 0.f;
    if (n < Nx) {
        const float4* xr = ((const float4*)d_xr) + (size_t)b * Nx * 2;
        float4 xn = xr[2 * n], rn = xr[2 * n + 1];
        int nn = numnb[n];
        const int4* nb4 = (const int4*)(nbr + n * Kx);
        const float4* wm4 = (const float4*)(wmat + n * Kx);
        int jk[Kx]; float wk[Kx];
#pragma unroll
        for (int q = 0; q < 4; q++) {
            int4 jv = nb4[q]; float4 wv = wm4[q];
            jk[q * 4 + 0] = jv.x; jk[q * 4 + 1] = jv.y; jk[q * 4 + 2] = jv.z; jk[q * 4 + 3] = jv.w;
            wk[q * 4 + 0] = (q * 4 + 0 < nn) ? wv.x : 0.f;
            wk[q * 4 + 1] = (q * 4 + 1 < nn) ? wv.y : 0.f;
            wk[q * 4 + 2] = (q * 4 + 2 < nn) ? wv.z : 0.f;
            wk[q * 4 + 3] = (q * 4 + 3 < nn) ? wv.w : 0.f;
        }
        float S00 = 0, S01 = 0, S02 = 0, S10 = 0, S11 = 0, S12 = 0, S20 = 0, S21 = 0, S22 = 0;
#pragma unroll
        for (int k = 0; k < Kx; k++) {
            float w = wk[k];
            if (w != 0.f) {             // masked edges: no gather, no smem, no S
                int j = jk[k];
                float4 xj = xr[2 * j], rj = xr[2 * j + 1];
                float dx = xn.x - xj.x, dy = xn.y - xj.y, dz = xn.z - xj.z;
                float cx = rn.x - rj.x, cy = rn.y - rj.y, cz = rn.z - rj.z;
                sh[(k * 6 + 0) * 128 + t] = dx; sh[(k * 6 + 1) * 128 + t] = dy; sh[(k * 6 + 2) * 128 + t] = dz;
                sh[(k * 6 + 3) * 128 + t] = cx; sh[(k * 6 + 4) * 128 + t] = cy; sh[(k * 6 + 5) * 128 + t] = cz;
                S00 += w * dx * cx; S01 += w * dx * cy; S02 += w * dx * cz;
                S10 += w * dy * cx; S11 += w * dy * cy; S12 += w * dy * cz;
                S20 += w * dz * cx; S21 += w * dz * cy; S22 += w * dz * cz;
            }
        }
        // Davenport/Horn 4x4: max eigenvector = quaternion of best-fit R (d -> c)
        float a[4][4], v[4][4];
        a[0][0] = S00 + S11 + S22;
        a[1][1] = S00 - S11 - S22;
        a[2][2] = S11 - S00 - S22;
        a[3][3] = S22 - S00 - S11;
        a[0][1] = a[1][0] = S12 - S21;
        a[0][2] = a[2][0] = S20 - S02;
        a[0][3] = a[3][0] = S01 - S10;
        a[1][2] = a[2][1] = S01 + S10;
        a[1][3] = a[3][1] = S02 + S20;
        a[2][3] = a[3][2] = S12 + S21;
#pragma unroll
        for (int i = 0; i < 4; i++)
#pragma unroll
            for (int j2 = 0; j2 < 4; j2++) v[i][j2] = (i == j2) ? 1.f : 0.f;
#pragma unroll
        for (int sw = 0; sw < 4; sw++) {
            jrot<0, 1>(a, v); jrot<0, 2>(a, v); jrot<0, 3>(a, v);
            jrot<1, 2>(a, v); jrot<1, 3>(a, v); jrot<2, 3>(a, v);
        }
        float best = a[0][0];
        float qw = v[0][0], qx = v[1][0], qy = v[2][0], qz = v[3][0];
#pragma unroll
        for (int m = 1; m < 4; m++)
            if (a[m][m] > best) {
                best = a[m][m];
                qw = v[0][m]; qx = v[1][m]; qy = v[2][m]; qz = v[3][m];
            }
        float inv = rsqrtf(qw * qw + qx * qx + qy * qy + qz * qz);
        qw *= inv; qx *= inv; qy *= inv; qz *= inv;
        float R00 = 1.f - 2.f * (qy * qy + qz * qz);
        float R01 = 2.f * (qx * qy - qw * qz);
        float R02 = 2.f * (qx * qz + qw * qy);
        float R10 = 2.f * (qx * qy + qw * qz);
        float R11 = 1.f - 2.f * (qx * qx + qz * qz);
        float R12 = 2.f * (qy * qz - qw * qx);
        float R20 = 2.f * (qx * qz - qw * qy);
        float R21 = 2.f * (qy * qz + qw * qx);
        float R22 = 1.f - 2.f * (qx * qx + qy * qy);

        float an = area[n];
        float coef = 2.f * an * invNK;
        float gx = 0.f, gy = 0.f, gz = 0.f, es = 0.f;
        float4* gb4 = ((float4*)d_gflat) + (size_t)b * Nx;
#pragma unroll
        for (int k = 0; k < Kx; k++) {
            float w = wk[k];
            if (w != 0.f) {
                float dx = sh[(k * 6 + 0) * 128 + t], dy = sh[(k * 6 + 1) * 128 + t], dz = sh[(k * 6 + 2) * 128 + t];
                float cx = sh[(k * 6 + 3) * 128 + t], cy = sh[(k * 6 + 4) * 128 + t], cz = sh[(k * 6 + 5) * 128 + t];
                float r0 = cx - (R00 * dx + R01 * dy + R02 * dz);
                float r1 = cy - (R10 * dx + R11 * dy + R12 * dz);
                float r2 = cz - (R20 * dx + R21 * dy + R22 * dz);
                es += w * (r0 * r0 + r1 * r1 + r2 * r2);
                float g0 = coef * w * r0, g1 = coef * w * r1, g2 = coef * w * r2;
                gx += g0; gy += g1; gz += g2;
                atomicAdd(&gb4[jk[k]], make_float4(-g0, -g1, -g2, 0.f));
            }
        }
        atomicAdd(&gb4[n], make_float4(gx, gy, gz, 0.f));
        ev = an * es;
    }
    __syncthreads();
    sh[t] = ev;
    __syncthreads();
    for (int s = 64; s > 0; s >>= 1) {
        if (t < s) sh[t] += sh[t + s];
        __syncthreads();
    }
    if (t == 0) atomicAdd(&out[b], sh[0] * invNK);
}

// ---------------- g_h = g_flat @ W2^T (streams W2 again) ----------------
#define GHW 128
__global__ void __launch_bounds__(256, 2) k_gh(const float* __restrict__ W2) {
    __shared__ ull gs[8 * GHW];  // [p][jwin], 8 KB, conflict-free
    int t = threadIdx.x;
    int lane = t & 31, wrp = t >> 5;
    int k0 = blockIdx.x * 32 + wrp * 4;
    ull acc[4][8];
#pragma unroll
    for (int u = 0; u < 4; u++)
#pragma unroll
        for (int p = 0; p < 8; p++) acc[u][p] = 0ull;

    for (int jb = blockIdx.y * GHW; jb < NOx; jb += gridDim.y * GHW) {
        __syncthreads();
        for (int idx = t; idx < 8 * GHW; idx += 256) {
            int p = idx >> 7, jj = idx & (GHW - 1);
            int j = jb + jj;
            float v0 = 0.f, v1 = 0.f;
            if (j < NOx) {
                int n = j / 3, c = j - 3 * n;
                v0 = d_gflat[((size_t)(2 * p) * Nx + n) * 4 + c];
                v1 = d_gflat[((size_t)(2 * p + 1) * Nx + n) * 4 + c];
            }
            gs[idx] = pack2(v0, v1);
        }
        __syncthreads();
        float wv[4][4];
#pragma unroll
        for (int s = 0; s < 4; s++) {
            int j = min(jb + s * 32 + lane, NOx - 1);
            const float* wp = W2 + j;
#pragma unroll
            for (int u = 0; u < 4; u++) wv[s][u] = wp[(size_t)(k0 + u) * NOx];
        }
#pragma unroll
        for (int s = 0; s < 4; s++) {
            ull g[8];
#pragma unroll
            for (int p = 0; p < 8; p++) g[p] = gs[p * GHW + s * 32 + lane];
#pragma unroll
            for (int u = 0; u < 4; u++) {
                ull wpk = pack2(wv[s][u], wv[s][u]);
#pragma unroll
                for (int p = 0; p < 8; p++) acc[u][p] = ffma2(g[p], wpk, acc[u][p]);
            }
        }
    }
#pragma unroll
    for (int u = 0; u < 4; u++)
#pragma unroll
        for (int p = 0; p < 8; p++) {
            float x, y;
            unpack2(acc[u][p], x, y);
#pragma unroll
            for (int off = 16; off > 0; off >>= 1) {
                x += __shfl_xor_sync(0xFFFFFFFFu, x, off);
                y += __shfl_xor_sync(0xFFFFFFFFu, y, off);
            }
            if (lane == 0) {
                atomicAdd(&d_ghid[(2 * p) * Hx + k0 + u], x);
                atomicAdd(&d_ghid[(2 * p + 1) * Hx + k0 + u], y);
            }
        }
}

// ---------------- code_grad = (g_h * relu') @ W1^T ----------------
__global__ void __launch_bounds__(256) k_cgrad(float* __restrict__ out) {
    __shared__ float mg[128];
    int b = blockIdx.x, hg = blockIdx.y, t = threadIdx.x;
    if (t < 128) {
        int h = hg * 128 + t;
        mg[t] = d_ghid[b * Hx + h] * (d_h[h * Bx + b] > 0.f ? 1.f : 0.f);
    }
    __syncthreads();
    float acc = 0.f;
#pragma unroll 8
    for (int hh = 0; hh < 128; hh++) acc += mg[hh] * d_w1t[(hg * 128 + hh) * Lx + t];
    atomicAdd(&out[Bx + b * Lx + t], acc);
}

// ---------------- launch ----------------
extern "C" void kernel_launch(void* const* d_in, const int* in_sizes, int n_in,
                              void* d_out, int out_size) {
    const float* code = (const float*)d_in[0];
    const float* W1   = (const float*)d_in[1];
    const float* b1   = (const float*)d_in[2];
    const float* W2   = (const float*)d_in[3];
    const float* b2   = (const float*)d_in[4];
    const float* xyz  = (const float*)d_in[5];
    const float* wmat = (const float*)d_in[6];
    const float* area = (const float*)d_in[7];
    const int*   nbr  = (const int*)d_in[8];
    const int*   nnb  = (const int*)d_in[9];
    float* out = (float*)d_out;

    k_prep1<<<(Bx * Nx * 4 + 255) / 256, 256>>>(xyz);
    k_prep2<<<(Lx * Hx + 255) / 256, 256>>>(W1, out);
    k_hidden<<<Hx / 256, 256>>>(code, W1, b1);
    k_recon<<<dim3(37, 8), 256>>>(W2);            // launch #4 -> profiled next round
    k_comb<<<(Bx * Nx + 255) / 256, 256>>>(b2);
    k_arap<<<dim3((Nx + 127) / 128, Bx), 128>>>(wmat, area, nbr, nnb, out);
    k_gh<<<dim3(32, 9), 256>>>(W2);
    k_cgrad<<<dim3(Bx, 8), 256>>>(out);
    (void)in_sizes; (void)n_in; (void)out_size;
}

// round 14
// speedup vs baseline: 2.5334x; 1.2916x over previous
#include <cuda_runtime.h>

#define Bx 16
#define Nx 20000
#define Kx 16
#define Lx 256
#define Hx 1024
#define NOx 60000
#define NQ (NOx / 4)   // 15000 float4 per W2 row

typedef unsigned long long ull;

// ---------------- device scratch ----------------
__device__ float d_h[Hx * Bx];                 // hidden post-relu, [k*16+b]
__device__ float d_rflat[4 * Bx * NOx];        // recon partials [ky][b][j]  (15.4 MB)
__device__ float d_xr[Bx * Nx * 8];            // packed {x,y,z,0, rx,ry,rz,0} per (b,n)
__device__ float d_gflat[Bx * Nx * 4];         // grad wrt recon [b][n][4]
__device__ float d_ghid[Bx * Hx];              // [b][k]
__device__ float d_w1t[Hx * Lx];               // W1^T [h][l]

// ---------------- packed f32x2 helpers ----------------
static __device__ __forceinline__ ull pack2(float x, float y) {
    ull r;
    asm("mov.b64 %0,{%1,%2};" : "=l"(r) : "r"(__float_as_uint(x)), "r"(__float_as_uint(y)));
    return r;
}
static __device__ __forceinline__ void unpack2(ull v, float& x, float& y) {
    unsigned lo, hi;
    asm("mov.b64 {%0,%1},%2;" : "=r"(lo), "=r"(hi) : "l"(v));
    x = __uint_as_float(lo); y = __uint_as_float(hi);
}
static __device__ __forceinline__ ull ffma2(ull a, ull b, ull c) {
    ull d;
    asm("fma.rn.f32x2 %0,%1,%2,%3;" : "=l"(d) : "l"(a), "l"(b), "l"(c));
    return d;
}

// ---------------- prep + hidden fused (blocks 0..3 = hidden GEMM) ----------------
__global__ void __launch_bounds__(256) k_prep(const float* __restrict__ code,
                                              const float* __restrict__ W1,
                                              const float* __restrict__ b1,
                                              const float* __restrict__ xyz,
                                              float* __restrict__ out) {
    int t = threadIdx.x;
    if (blockIdx.x < 4) {
        __shared__ float cs[Bx * Lx];
        for (int i = t; i < Bx * Lx; i += 256) cs[i] = code[i];
        __syncthreads();
        int j = blockIdx.x * 256 + t;
        float acc[Bx];
        float bj = b1[j];
#pragma unroll
        for (int b = 0; b < Bx; b++) acc[b] = bj;
#pragma unroll 8
        for (int l = 0; l < Lx; l++) {
            float w = W1[l * Hx + j];
#pragma unroll
            for (int b = 0; b < Bx; b++) acc[b] += cs[b * Lx + l] * w;
        }
#pragma unroll
        for (int b = 0; b < Bx; b++) d_h[j * Bx + b] = fmaxf(acc[b], 0.f);
        return;
    }
    int i = (blockIdx.x - 4) * 256 + t;
    if (i < Bx * Nx * 4) d_gflat[i] = 0.f;
    if (i < Bx * Nx) {
        float4 v;
        v.x = xyz[i * 3 + 0]; v.y = xyz[i * 3 + 1]; v.z = xyz[i * 3 + 2]; v.w = 0.f;
        ((float4*)d_xr)[i * 2] = v;
    }
    if (i < Lx * Hx) { int l = i >> 10, h = i & 1023; d_w1t[h * Lx + l] = W1[i]; }
    if (i < Bx * Hx) d_ghid[i] = 0.f;
    if (i < Bx + Bx * Lx) out[i] = 0.f;
}

// ---------------- recon partials: grid (4 ky, 74 q-blocks), exact work ----------------
__global__ void __launch_bounds__(256, 2) k_recon(const float* __restrict__ W2) {
    __shared__ __align__(16) float hs[256 * 16];  // 16 KB h chunk [k][b]
    int t = threadIdx.x;
    int ky = blockIdx.x;                          // 4 chunks of 256 k (fast dim -> SM interleave)
    for (int i = t; i < 256 * 16; i += 256) hs[i] = d_h[ky * 256 * 16 + i];
    __syncthreads();
    int q = blockIdx.y * 256 + t;
    if (q >= NQ) return;                          // idle warps free their issue slots
    const ulonglong2* hu = (const ulonglong2*)hs;
    const float4* wq = ((const float4*)W2) + (size_t)(ky * 256) * NQ;
    ull acc[4][8];
#pragma unroll
    for (int jj = 0; jj < 4; jj++)
#pragma unroll
        for (int p = 0; p < 8; p++) acc[jj][p] = 0ull;

    for (int k4 = 0; k4 < 256; k4 += 4) {
        float4 w[4];
#pragma unroll
        for (int u = 0; u < 4; u++) w[u] = wq[(size_t)(k4 + u) * NQ + q];
#pragma unroll
        for (int u = 0; u < 4; u++) {
            int k = k4 + u;
            ulonglong2 ha = hu[k * 4 + 0], hb = hu[k * 4 + 1];
            ulonglong2 hc = hu[k * 4 + 2], hd = hu[k * 4 + 3];
            ull hv[8] = {ha.x, ha.y, hb.x, hb.y, hc.x, hc.y, hd.x, hd.y};
            ull w0 = pack2(w[u].x, w[u].x), w1 = pack2(w[u].y, w[u].y);
            ull w2v = pack2(w[u].z, w[u].z), w3 = pack2(w[u].w, w[u].w);
#pragma unroll
            for (int p = 0; p < 8; p++) {
                acc[0][p] = ffma2(hv[p], w0, acc[0][p]);
                acc[1][p] = ffma2(hv[p], w1, acc[1][p]);
                acc[2][p] = ffma2(hv[p], w2v, acc[2][p]);
                acc[3][p] = ffma2(hv[p], w3, acc[3][p]);
            }
        }
    }
    float* base = d_rflat + (size_t)ky * Bx * NOx + 4 * q;
#pragma unroll
    for (int p = 0; p < 8; p++) {
        float x0, y0, x1, y1, x2, y2, x3, y3;
        unpack2(acc[0][p], x0, y0);
        unpack2(acc[1][p], x1, y1);
        unpack2(acc[2][p], x2, y2);
        unpack2(acc[3][p], x3, y3);
        *(float4*)(base + (size_t)(2 * p) * NOx)     = make_float4(x0, x1, x2, x3);
        *(float4*)(base + (size_t)(2 * p + 1) * NOx) = make_float4(y0, y1, y2, y3);
    }
}

// ---------------- combine flat partials + bias -> packed xr slots 4..7 ----------------
__global__ void k_comb(const float* __restrict__ b2) {
    int i = blockIdx.x * 256 + threadIdx.x;  // b*Nx + n
    if (i >= Bx * Nx) return;
    int b = i / Nx, n = i - b * Nx;
    float x = 0.f, y = 0.f, z = 0.f;
#pragma unroll
    for (int ky = 0; ky < 4; ky++) {
        const float* p = d_rflat + (size_t)(ky * Bx + b) * NOx + 3 * n;
        x += p[0]; y += p[1]; z += p[2];
    }
    float4 r;
    r.x = x + b2[n * 3 + 0];
    r.y = y + b2[n * 3 + 1];
    r.z = z + b2[n * 3 + 2];
    r.w = 0.f;
    ((float4*)d_xr)[i * 2 + 1] = r;
}

// ---------------- Jacobi rotation on symmetric 4x4, compile-time (P,Q) ----------------
template <int P, int Q>
static __device__ __forceinline__ void jrot(float a[4][4], float v[4][4]) {
    float apq = a[P][Q];
    if (apq != 0.f) {
        float theta = __fdividef(0.5f * (a[Q][Q] - a[P][P]), apq);
        float tt = __fdividef(copysignf(1.f, theta), fabsf(theta) + sqrtf(theta * theta + 1.f));
        float c = rsqrtf(tt * tt + 1.f);
        float s = tt * c;
        a[P][P] -= tt * apq;
        a[Q][Q] += tt * apq;
        a[P][Q] = 0.f; a[Q][P] = 0.f;
#pragma unroll
        for (int r = 0; r < 4; r++) {
            if (r == P || r == Q) continue;
            float arp = a[r][P], arq = a[r][Q];
            float nrp = c * arp - s * arq;
            float nrq = s * arp + c * arq;
            a[r][P] = nrp; a[P][r] = nrp;
            a[r][Q] = nrq; a[Q][r] = nrq;
        }
#pragma unroll
        for (int r = 0; r < 4; r++) {
            float vrp = v[r][P], vrq = v[r][Q];
            v[r][P] = c * vrp - s * vrq;
            v[r][Q] = s * vrp + c * vrq;
        }
    }
}

// ---------------- fused per-vertex ARAP: predicated on w!=0 ----------------
__global__ void __launch_bounds__(128, 4) k_arap(const float* __restrict__ wmat,
                                                 const float* __restrict__ area,
                                                 const int* __restrict__ nbr,
                                                 const int* __restrict__ numnb,
                                                 float* __restrict__ out) {
    __shared__ float sh[96 * 128];  // [slot][tid]: 6 floats per nbr, 16 nbrs = 48 KB
    const float invNK = 1.f / (float)(Nx * Kx);
    int t = threadIdx.x;
    int n = blockIdx.x * 128 + t;
    int b = blockIdx.y;
    float ev = 0.f;
    if (n < Nx) {
        const float4* xr = ((const float4*)d_xr) + (size_t)b * Nx * 2;
        float4 xn = xr[2 * n], rn = xr[2 * n + 1];
        int nn = numnb[n];
        const int4* nb4 = (const int4*)(nbr + n * Kx);
        const float4* wm4 = (const float4*)(wmat + n * Kx);
        int jk[Kx]; float wk[Kx];
#pragma unroll
        for (int q = 0; q < 4; q++) {
            int4 jv = nb4[q]; float4 wv = wm4[q];
            jk[q * 4 + 0] = jv.x; jk[q * 4 + 1] = jv.y; jk[q * 4 + 2] = jv.z; jk[q * 4 + 3] = jv.w;
            wk[q * 4 + 0] = (q * 4 + 0 < nn) ? wv.x : 0.f;
            wk[q * 4 + 1] = (q * 4 + 1 < nn) ? wv.y : 0.f;
            wk[q * 4 + 2] = (q * 4 + 2 < nn) ? wv.z : 0.f;
            wk[q * 4 + 3] = (q * 4 + 3 < nn) ? wv.w : 0.f;
        }
        float S00 = 0, S01 = 0, S02 = 0, S10 = 0, S11 = 0, S12 = 0, S20 = 0, S21 = 0, S22 = 0;
#pragma unroll
        for (int k = 0; k < Kx; k++) {
            float w = wk[k];
            if (w != 0.f) {
                int j = jk[k];
                float4 xj = xr[2 * j], rj = xr[2 * j + 1];
                float dx = xn.x - xj.x, dy = xn.y - xj.y, dz = xn.z - xj.z;
                float cx = rn.x - rj.x, cy = rn.y - rj.y, cz = rn.z - rj.z;
                sh[(k * 6 + 0) * 128 + t] = dx; sh[(k * 6 + 1) * 128 + t] = dy; sh[(k * 6 + 2) * 128 + t] = dz;
                sh[(k * 6 + 3) * 128 + t] = cx; sh[(k * 6 + 4) * 128 + t] = cy; sh[(k * 6 + 5) * 128 + t] = cz;
                S00 += w * dx * cx; S01 += w * dx * cy; S02 += w * dx * cz;
                S10 += w * dy * cx; S11 += w * dy * cy; S12 += w * dy * cz;
                S20 += w * dz * cx; S21 += w * dz * cy; S22 += w * dz * cz;
            }
        }
        float a[4][4], v[4][4];
        a[0][0] = S00 + S11 + S22;
        a[1][1] = S00 - S11 - S22;
        a[2][2] = S11 - S00 - S22;
        a[3][3] = S22 - S00 - S11;
        a[0][1] = a[1][0] = S12 - S21;
        a[0][2] = a[2][0] = S20 - S02;
        a[0][3] = a[3][0] = S01 - S10;
        a[1][2] = a[2][1] = S01 + S10;
        a[1][3] = a[3][1] = S02 + S20;
        a[2][3] = a[3][2] = S12 + S21;
#pragma unroll
        for (int i = 0; i < 4; i++)
#pragma unroll
            for (int j2 = 0; j2 < 4; j2++) v[i][j2] = (i == j2) ? 1.f : 0.f;
#pragma unroll
        for (int sw = 0; sw < 4; sw++) {
            jrot<0, 1>(a, v); jrot<0, 2>(a, v); jrot<0, 3>(a, v);
            jrot<1, 2>(a, v); jrot<1, 3>(a, v); jrot<2, 3>(a, v);
        }
        float best = a[0][0];
        float qw = v[0][0], qx = v[1][0], qy = v[2][0], qz = v[3][0];
#pragma unroll
        for (int m = 1; m < 4; m++)
            if (a[m][m] > best) {
                best = a[m][m];
                qw = v[0][m]; qx = v[1][m]; qy = v[2][m]; qz = v[3][m];
            }
        float inv = rsqrtf(qw * qw + qx * qx + qy * qy + qz * qz);
        qw *= inv; qx *= inv; qy *= inv; qz *= inv;
        float R00 = 1.f - 2.f * (qy * qy + qz * qz);
        float R01 = 2.f * (qx * qy - qw * qz);
        float R02 = 2.f * (qx * qz + qw * qy);
        float R10 = 2.f * (qx * qy + qw * qz);
        float R11 = 1.f - 2.f * (qx * qx + qz * qz);
        float R12 = 2.f * (qy * qz - qw * qx);
        float R20 = 2.f * (qx * qz - qw * qy);
        float R21 = 2.f * (qy * qz + qw * qx);
        float R22 = 1.f - 2.f * (qx * qx + qy * qy);

        float an = area[n];
        float coef = 2.f * an * invNK;
        float gx = 0.f, gy = 0.f, gz = 0.f, es = 0.f;
        float4* gb4 = ((float4*)d_gflat) + (size_t)b * Nx;
#pragma unroll
        for (int k = 0; k < Kx; k++) {
            float w = wk[k];
            if (w != 0.f) {
                float dx = sh[(k * 6 + 0) * 128 + t], dy = sh[(k * 6 + 1) * 128 + t], dz = sh[(k * 6 + 2) * 128 + t];
                float cx = sh[(k * 6 + 3) * 128 + t], cy = sh[(k * 6 + 4) * 128 + t], cz = sh[(k * 6 + 5) * 128 + t];
                float r0 = cx - (R00 * dx + R01 * dy + R02 * dz);
                float r1 = cy - (R10 * dx + R11 * dy + R12 * dz);
                float r2 = cz - (R20 * dx + R21 * dy + R22 * dz);
                es += w * (r0 * r0 + r1 * r1 + r2 * r2);
                float g0 = coef * w * r0, g1 = coef * w * r1, g2 = coef * w * r2;
                gx += g0; gy += g1; gz += g2;
                atomicAdd(&gb4[jk[k]], make_float4(-g0, -g1, -g2, 0.f));
            }
        }
        atomicAdd(&gb4[n], make_float4(gx, gy, gz, 0.f));
        ev = an * es;
    }
    __syncthreads();
    sh[t] = ev;
    __syncthreads();
    for (int s = 64; s > 0; s >>= 1) {
        if (t < s) sh[t] += sh[t + s];
        __syncthreads();
    }
    if (t == 0) atomicAdd(&out[b], sh[0] * invNK);
}

// ---------------- g_h = g_flat @ W2^T (streams W2 again) ----------------
#define GHW 256
__global__ void __launch_bounds__(256, 2) k_gh(const float* __restrict__ W2) {
    __shared__ ull gs[8 * GHW];  // [p][jwin], 16 KB, conflict-free
    int t = threadIdx.x;
    int lane = t & 31, wrp = t >> 5;
    int k0 = blockIdx.x * 32 + wrp * 4;
    ull acc[4][8];
#pragma unroll
    for (int u = 0; u < 4; u++)
#pragma unroll
        for (int p = 0; p < 8; p++) acc[u][p] = 0ull;

    for (int jb = blockIdx.y * GHW; jb < NOx; jb += gridDim.y * GHW) {
        __syncthreads();
#pragma unroll
        for (int it = 0; it < 8; it++) {
            int p = it, jj = t;
            int j = jb + jj;
            float v0 = 0.f, v1 = 0.f;
            if (j < NOx) {
                int n = j / 3, c = j - 3 * n;
                v0 = d_gflat[((size_t)(2 * p) * Nx + n) * 4 + c];
                v1 = d_gflat[((size_t)(2 * p + 1) * Nx + n) * 4 + c];
            }
            gs[p * GHW + jj] = pack2(v0, v1);
        }
        __syncthreads();
#pragma unroll 1
        for (int s4 = 0; s4 < 8; s4 += 4) {
            float wv[4][4];
#pragma unroll
            for (int s = 0; s < 4; s++) {
                int j = min(jb + (s4 + s) * 32 + lane, NOx - 1);
                const float* wp = W2 + j;
#pragma unroll
                for (int u = 0; u < 4; u++) wv[s][u] = wp[(size_t)(k0 + u) * NOx];
            }
#pragma unroll
            for (int s = 0; s < 4; s++) {
                ull g[8];
#pragma unroll
                for (int p = 0; p < 8; p++) g[p] = gs[p * GHW + (s4 + s) * 32 + lane];
#pragma unroll
                for (int u = 0; u < 4; u++) {
                    ull wpk = pack2(wv[s][u], wv[s][u]);
#pragma unroll
                    for (int p = 0; p < 8; p++) acc[u][p] = ffma2(g[p], wpk, acc[u][p]);
                }
            }
        }
    }
#pragma unroll
    for (int u = 0; u < 4; u++)
#pragma unroll
        for (int p = 0; p < 8; p++) {
            float x, y;
            unpack2(acc[u][p], x, y);
#pragma unroll
            for (int off = 16; off > 0; off >>= 1) {
                x += __shfl_xor_sync(0xFFFFFFFFu, x, off);
                y += __shfl_xor_sync(0xFFFFFFFFu, y, off);
            }
            if (lane == 0) {
                atomicAdd(&d_ghid[(2 * p) * Hx + k0 + u], x);
                atomicAdd(&d_ghid[(2 * p + 1) * Hx + k0 + u], y);
            }
        }
}

// ---------------- code_grad = (g_h * relu') @ W1^T ----------------
__global__ void __launch_bounds__(256) k_cgrad(float* __restrict__ out) {
    __shared__ float mg[128];
    int b = blockIdx.x, hg = blockIdx.y, t = threadIdx.x;
    if (t < 128) {
        int h = hg * 128 + t;
        mg[t] = d_ghid[b * Hx + h] * (d_h[h * Bx + b] > 0.f ? 1.f : 0.f);
    }
    __syncthreads();
    float acc = 0.f;
#pragma unroll 8
    for (int hh = 0; hh < 128; hh++) acc += mg[hh] * d_w1t[(hg * 128 + hh) * Lx + t];
    atomicAdd(&out[Bx + b * Lx + t], acc);
}

// ---------------- launch ----------------
extern "C" void kernel_launch(void* const* d_in, const int* in_sizes, int n_in,
                              void* d_out, int out_size) {
    const float* code = (const float*)d_in[0];
    const float* W1   = (const float*)d_in[1];
    const float* b1   = (const float*)d_in[2];
    const float* W2   = (const float*)d_in[3];
    const float* b2   = (const float*)d_in[4];
    const float* xyz  = (const float*)d_in[5];
    const float* wmat = (const float*)d_in[6];
    const float* area = (const float*)d_in[7];
    const int*   nbr  = (const int*)d_in[8];
    const int*   nnb  = (const int*)d_in[9];
    float* out = (float*)d_out;

    k_prep<<<4 + (Bx * Nx * 4 + 255) / 256, 256>>>(code, W1, b1, xyz, out);
    k_recon<<<dim3(4, 74), 256>>>(W2);
    k_comb<<<(Bx * Nx + 255) / 256, 256>>>(b2);
    k_arap<<<dim3((Nx + 127) / 128, Bx), 128>>>(wmat, area, nbr, nnb, out);  // slot 4 -> profiled
    k_gh<<<dim3(32, 9), 256>>>(W2);
    k_cgrad<<<dim3(Bx, 8), 256>>>(out);
    (void)in_sizes; (void)n_in; (void)out_size;
}